// round 6
// baseline (speedup 1.0000x reference)
#include <cuda_runtime.h>
#include <cuda_bf16.h>
#include <math.h>
#include <stdint.h>

// Problem constants
#define BB 4
#define SS 256
#define DD 256
#define VV 128
#define EE 64
#define CC 192
#define LN_EPS 1e-3f

// main-kernel smem byte offsets (padded strides: x 72 bf16/row, w 72 bf16/row, dbuf 65 f32/row)
#define XH_OFF 0
#define XL_OFF 18432
#define WH_OFF 36864
#define WL_OFF 64512
#define DB_OFF 92160
#define AUX    125440
#define OFF_QS   (AUX)
#define OFF_WDS  (AUX + 256)
#define OFF_S1K  (AUX + 512)
#define OFF_S2K  (AUX + 768)
#define OFF_S1V  (AUX + 1024)
#define OFF_S2V  (AUX + 1280)
#define OFF_BES  (AUX + 1536)
#define SMEM_MAIN (AUX + 1792)   // 127232 bytes

// ---------------- device scratch ----------------
__device__ __align__(16) float g_Wall[CC * 192];
__device__ float g_S1k[64], g_S2k[64], g_S1v[64], g_S2v[64];
__device__ float g_q[BB * DD * 64];
__device__ float g_wd[BB * DD * 64];
__device__ float g_opart[BB * DD * 2 * 64];
__device__ __align__(16) float g_G1[BB * SS * 192];
__device__ float g_sv[BB * SS], g_sq[BB * SS];
__device__ __align__(16) __nv_bfloat16 g_WTh[192 * 72];  // W2^T hi, [n][k] padded
__device__ __align__(16) __nv_bfloat16 g_WTl[192 * 72];  // W2^T lo

// ---------------- mma.sync helper (baseline sm_80+ PTX, runs on sm_103 tensor pipe) ----------------
__device__ __forceinline__ void mma16816(float* c, const uint32_t* a, const uint32_t* b) {
    asm volatile(
        "mma.sync.aligned.m16n8k16.row.col.f32.bf16.bf16.f32 "
        "{%0,%1,%2,%3}, {%4,%5,%6,%7}, {%8,%9}, {%0,%1,%2,%3};"
        : "+f"(c[0]), "+f"(c[1]), "+f"(c[2]), "+f"(c[3])
        : "r"(a[0]), "r"(a[1]), "r"(a[2]), "r"(a[3]), "r"(b[0]), "r"(b[1]));
}

// ---------------- prep: build fused weight matrix ----------------
__global__ void prep_wall(const float* __restrict__ g_in, const float* __restrict__ Wk,
                          const float* __restrict__ Wv, const float* __restrict__ We) {
    int c = blockIdx.x;     // 0..191
    int j = threadIdx.x;    // 0..191
    float g = g_in[c];
    float val;
    if (j < 64)        val = g * Wk[c * 64 + j];
    else if (j < 128)  val = g * Wv[c * 64 + (j - 64)];
    else {
        int t = j - 128;
        val = (c < 128) ? We[c * 64 + t] : We[(c + 128) * 64 + t];
    }
    g_Wall[c * 192 + j] = val;
}

__global__ void prep_sums(const float* __restrict__ g_in, const float* __restrict__ b_in,
                          const float* __restrict__ Wk, const float* __restrict__ bk,
                          const float* __restrict__ Wv, const float* __restrict__ bv) {
    int tid = threadIdx.x;  // 128 threads
    if (tid < 64) {
        int j = tid;
        float s1 = 0.f, s2 = 0.f;
        for (int c = 0; c < CC; c++) {
            float w = Wk[c * 64 + j];
            s1 += g_in[c] * w;
            s2 += b_in[c] * w;
        }
        g_S1k[j] = s1;
        g_S2k[j] = s2 + bk[j];
    } else {
        int j = tid - 64;
        float s1 = 0.f, s2 = 0.f;
        for (int c = 0; c < CC; c++) {
            float w = Wv[c * 64 + j];
            s1 += g_in[c] * w;
            s2 += b_in[c] * w;
        }
        g_S1v[j] = s1;
        g_S2v[j] = s2 + bv[j];
    }
}

// ---------------- prep: bf16 hi/lo image of W2^T [192 n][72 pad k] ----------------
__global__ void prep_wt() {
    int n = blockIdx.x;     // 0..191
    int k = threadIdx.x;    // 0..63
    float w = g_Wall[(128 + k) * 192 + n];
    __nv_bfloat16 wh = __float2bfloat16(w);
    __nv_bfloat16 wl = __float2bfloat16(w - __bfloat162float(wh));
    g_WTh[n * 72 + k] = wh;
    g_WTl[n * 72 + k] = wl;
    if (k >= 56) {  // zero the pad tail (never read by MMA, but keep smem copies defined)
        g_WTh[n * 72 + 8 + k] = __float2bfloat16(0.f);
        g_WTl[n * 72 + 8 + k] = __float2bfloat16(0.f);
    }
}

// ---------------- G1 = Vsrc @ Wall[0:128,:]  (+ row sums for LN) ----------------
__global__ void __launch_bounds__(128) g1_kernel(const float* __restrict__ Vsrc) {
    extern __shared__ float smf[];
    float* xt = smf;           // [128 c][8 r]
    float* ws = smf + 1024;    // [64 c][192 n]
    int bs0 = blockIdx.x * 8;
    int tid = threadIdx.x;
    int tx = tid & 15, ty = tid >> 4;

    for (int idx = tid; idx < 1024; idx += 128) {
        int c = idx & 127, r = idx >> 7;
        xt[c * 8 + r] = Vsrc[(bs0 + r) * VV + c];
    }
    __syncthreads();
    if (tid < 8) {
        float s = 0.f, ss = 0.f;
        for (int c = 0; c < VV; c++) {
            float x = xt[c * 8 + tid];
            s += x; ss += x * x;
        }
        g_sv[bs0 + tid] = s;
        g_sq[bs0 + tid] = ss;
    }

    float acc[12];
    #pragma unroll
    for (int i = 0; i < 12; i++) acc[i] = 0.f;

    for (int h = 0; h < 2; h++) {
        __syncthreads();
        const float4* src = (const float4*)(g_Wall + h * 64 * 192);
        float4* dst = (float4*)ws;
        for (int idx = tid; idx < 3072; idx += 128) dst[idx] = src[idx];
        __syncthreads();
        #pragma unroll 4
        for (int c = 0; c < 64; c++) {
            float x = xt[(h * 64 + c) * 8 + ty];
            const float* wr = ws + c * 192 + tx;
            #pragma unroll
            for (int i = 0; i < 12; i++) acc[i] = fmaf(x, wr[i * 16], acc[i]);
        }
    }
    float* gout = g_G1 + (size_t)(bs0 + ty) * 192 + tx;
    #pragma unroll
    for (int i = 0; i < 12; i++) gout[i * 16] = acc[i];
}

// ---------------- per-(b,d): LN(V_dst) -> q, and wd GEMV ----------------
__global__ void __launch_bounds__(128) qwd_kernel(
    const float* __restrict__ Vdst, const float* __restrict__ g_vd,
    const float* __restrict__ b_vd, const float* __restrict__ Wq,
    const float* __restrict__ bq, const float* __restrict__ We) {
    __shared__ float vrow[VV];
    __shared__ float vn[VV];
    __shared__ float rsum[4], rsq[4];
    __shared__ float smu, srstd;

    int bd = blockIdx.x;
    int tid = threadIdx.x;
    float x = Vdst[bd * VV + tid];
    vrow[tid] = x;

    float s = x, ss = x * x;
    for (int o = 16; o; o >>= 1) {
        s  += __shfl_down_sync(0xffffffffu, s, o);
        ss += __shfl_down_sync(0xffffffffu, ss, o);
    }
    if ((tid & 31) == 0) { rsum[tid >> 5] = s; rsq[tid >> 5] = ss; }
    __syncthreads();
    if (tid == 0) {
        float S = rsum[0] + rsum[1] + rsum[2] + rsum[3];
        float Q = rsq[0] + rsq[1] + rsq[2] + rsq[3];
        float m = S * (1.f / VV);
        float var = Q * (1.f / VV) - m * m;
        smu = m;
        srstd = rsqrtf(var + LN_EPS);
    }
    __syncthreads();
    vn[tid] = (x - smu) * srstd * g_vd[tid] + b_vd[tid];
    __syncthreads();

    if (tid < 64) {
        float q = bq[tid];
        #pragma unroll 4
        for (int j = 0; j < VV; j++) q += vn[j] * Wq[j * 64 + tid];
        g_q[bd * 64 + tid] = fmaxf(q, 0.f);
    } else {
        int t = tid - 64;
        float w = 0.f;
        #pragma unroll 4
        for (int j = 0; j < VV; j++) w += vrow[j] * We[(128 + j) * 64 + t];
        g_wd[bd * 64 + t] = w;
    }
}

// ---------------- A_new == 1.0 exactly ----------------
__global__ void fill_a(float* __restrict__ outA) {
    int idx = blockIdx.x * 1024 + threadIdx.x;
    outA[idx] = 1.0f;
}

// ---------------- main fused kernel: one (b, d, s-half of 128) per block ----------------
// D[128,192] = X[128,64] @ W2[64,192] via mma.sync bf16 3-term split, fp32 accum.
__global__ void __launch_bounds__(128) main_kernel(
    const float* __restrict__ Egl, const float* __restrict__ A,
    const float* __restrict__ be, float* __restrict__ outE) {
    extern __shared__ __align__(16) unsigned char smm[];
    int tid = threadIdx.x;
    int lane = tid & 31, wid = tid >> 5;
    int bx = blockIdx.x;
    int shalf = bx & 1, d = (bx >> 1) & 255, b = bx >> 9;
    int s0 = shalf * 128;
    int bd = b * DD + d;

    float* qs  = (float*)(smm + OFF_QS);
    float* wds = (float*)(smm + OFF_WDS);
    float* s1k = (float*)(smm + OFF_S1K);
    float* s2k = (float*)(smm + OFF_S2K);
    float* s1v = (float*)(smm + OFF_S1V);
    float* s2v = (float*)(smm + OFF_S2V);
    float* bes = (float*)(smm + OFF_BES);
    float* db  = (float*)(smm + DB_OFF);
    if (tid < 64) {
        qs[tid]  = g_q[bd * 64 + tid];
        wds[tid] = g_wd[bd * 64 + tid];
        s1k[tid] = g_S1k[tid]; s2k[tid] = g_S2k[tid];
        s1v[tid] = g_S1v[tid]; s2v[tid] = g_S2v[tid];
        bes[tid] = be[tid];
    }

    // stage W2^T hi/lo (2 x 27648 B) into smem
    {
        const uint4* sh = (const uint4*)g_WTh;
        const uint4* sl = (const uint4*)g_WTl;
        uint4* dh = (uint4*)(smm + WH_OFF);
        uint4* dl = (uint4*)(smm + WL_OFF);
        #pragma unroll 4
        for (int i = tid; i < 1728; i += 128) { dh[i] = sh[i]; dl[i] = sl[i]; }
    }

    // per-thread: load E row r, split to bf16 hi/lo into padded smem; row sums
    int r = tid;
    size_t bs = (size_t)(b * SS + s0 + r);
    const float4* ep = (const float4*)(Egl + (bs * DD + d) * EE);
    float se = 0.f, sq = 0.f;
    #pragma unroll
    for (int i = 0; i < 8; i++) {
        float4 u0 = __ldg(ep + 2 * i), u1 = __ldg(ep + 2 * i + 1);
        float x[8] = {u0.x, u0.y, u0.z, u0.w, u1.x, u1.y, u1.z, u1.w};
        #pragma unroll
        for (int t = 0; t < 4; t++) {
            float a0 = x[2 * t], a1 = x[2 * t + 1];
            se += a0 + a1; sq += a0 * a0 + a1 * a1;
            __nv_bfloat16 h0 = __float2bfloat16(a0), h1 = __float2bfloat16(a1);
            __nv_bfloat16 l0 = __float2bfloat16(a0 - __bfloat162float(h0));
            __nv_bfloat16 l1 = __float2bfloat16(a1 - __bfloat162float(h1));
            __nv_bfloat162 ph; ph.x = h0; ph.y = h1;
            __nv_bfloat162 pl; pl.x = l0; pl.y = l1;
            int col = i * 8 + t * 2;
            *(uint32_t*)(smm + XH_OFF + (r * 72 + col) * 2) = *(uint32_t*)&ph;
            *(uint32_t*)(smm + XL_OFF + (r * 72 + col) * 2) = *(uint32_t*)&pl;
        }
    }
    float av = __ldg(A + bs * DD + d);
    float mu = (av * g_sv[bs] + se) * (1.f / CC);
    float msq = (av * av * g_sq[bs] + sq) * (1.f / CC);
    float rstd = rsqrtf(msq - mu * mu + LN_EPS);
    __syncthreads();

    // ---- load A fragments once (rows = wid*32 + mt*16 + {g, g+8}) ----
    int g = lane >> 2, tc = lane & 3;
    uint32_t ahf[2][4][4], alf[2][4][4];
    #pragma unroll
    for (int mt = 0; mt < 2; mt++) {
        int r0 = wid * 32 + mt * 16 + g;
        #pragma unroll
        for (int ks = 0; ks < 4; ks++) {
            int c0 = tc * 2 + 16 * ks;
            ahf[mt][ks][0] = *(const uint32_t*)(smm + XH_OFF + (r0 * 72 + c0) * 2);
            ahf[mt][ks][1] = *(const uint32_t*)(smm + XH_OFF + ((r0 + 8) * 72 + c0) * 2);
            ahf[mt][ks][2] = *(const uint32_t*)(smm + XH_OFF + (r0 * 72 + c0 + 8) * 2);
            ahf[mt][ks][3] = *(const uint32_t*)(smm + XH_OFF + ((r0 + 8) * 72 + c0 + 8) * 2);
            alf[mt][ks][0] = *(const uint32_t*)(smm + XL_OFF + (r0 * 72 + c0) * 2);
            alf[mt][ks][1] = *(const uint32_t*)(smm + XL_OFF + ((r0 + 8) * 72 + c0) * 2);
            alf[mt][ks][2] = *(const uint32_t*)(smm + XL_OFF + (r0 * 72 + c0 + 8) * 2);
            alf[mt][ks][3] = *(const uint32_t*)(smm + XL_OFF + ((r0 + 8) * 72 + c0 + 8) * 2);
        }
    }

    const float* G1r = g_G1 + bs * 192;
    float sc[8];
    #pragma unroll
    for (int h = 0; h < 8; h++) sc[h] = 0.f;

    #pragma unroll 1
    for (int p = 0; p < 3; p++) {
        // ---- GEMM phase p: cols p*64 .. p*64+63 into dbuf ----
        #pragma unroll 1
        for (int nt = 0; nt < 8; nt++) {
            int n = p * 64 + nt * 8 + g;
            uint32_t bhf[4][2], blf[4][2];
            #pragma unroll
            for (int ks = 0; ks < 4; ks++) {
                int kk = tc * 2 + 16 * ks;
                bhf[ks][0] = *(const uint32_t*)(smm + WH_OFF + (n * 72 + kk) * 2);
                bhf[ks][1] = *(const uint32_t*)(smm + WH_OFF + (n * 72 + kk + 8) * 2);
                blf[ks][0] = *(const uint32_t*)(smm + WL_OFF + (n * 72 + kk) * 2);
                blf[ks][1] = *(const uint32_t*)(smm + WL_OFF + (n * 72 + kk + 8) * 2);
            }
            float cHH[2][4], cLH[2][4], cHL[2][4];
            #pragma unroll
            for (int mt = 0; mt < 2; mt++)
                #pragma unroll
                for (int i = 0; i < 4; i++) { cHH[mt][i] = 0.f; cLH[mt][i] = 0.f; cHL[mt][i] = 0.f; }
            #pragma unroll
            for (int ks = 0; ks < 4; ks++) {
                #pragma unroll
                for (int mt = 0; mt < 2; mt++) {
                    mma16816(cHH[mt], ahf[mt][ks], bhf[ks]);
                    mma16816(cLH[mt], alf[mt][ks], bhf[ks]);
                    mma16816(cHL[mt], ahf[mt][ks], blf[ks]);
                }
            }
            #pragma unroll
            for (int mt = 0; mt < 2; mt++) {
                int r0 = wid * 32 + mt * 16 + g;
                int col = nt * 8 + tc * 2;
                db[r0 * 65 + col]           = cHH[mt][0] + cLH[mt][0] + cHL[mt][0];
                db[r0 * 65 + col + 1]       = cHH[mt][1] + cLH[mt][1] + cHL[mt][1];
                db[(r0 + 8) * 65 + col]     = cHH[mt][2] + cLH[mt][2] + cHL[mt][2];
                db[(r0 + 8) * 65 + col + 1] = cHH[mt][3] + cLH[mt][3] + cHL[mt][3];
            }
        }
        __syncthreads();

        // ---- epilogue phase p (per-thread row r) ----
        if (p == 0) {
            #pragma unroll
            for (int jj = 0; jj < 16; jj++) {
                float4 gg = __ldg((const float4*)G1r + jj);
                float gv[4] = {gg.x, gg.y, gg.z, gg.w};
                #pragma unroll
                for (int u = 0; u < 4; u++) {
                    int j = jj * 4 + u;
                    float yf = av * gv[u] + db[r * 65 + j];
                    float kk = fmaxf(rstd * (yf - mu * s1k[j]) + s2k[j], 0.f);
                    sc[j >> 3] += qs[j] * kk;
                }
            }
            float mx = sc[0] * 0.35355339059327373f;
            #pragma unroll
            for (int h = 0; h < 8; h++) { sc[h] *= 0.35355339059327373f; mx = fmaxf(mx, sc[h]); }
            float sum = 0.f;
            #pragma unroll
            for (int h = 0; h < 8; h++) { sc[h] = __expf(sc[h] - mx); sum += sc[h]; }
            float inv = 1.f / sum;
            #pragma unroll
            for (int h = 0; h < 8; h++) sc[h] *= inv;
            __syncthreads();
        } else if (p == 1) {
            #pragma unroll
            for (int jj = 0; jj < 16; jj++) {
                float4 gg = __ldg((const float4*)(G1r + 64) + jj);
                float gv[4] = {gg.x, gg.y, gg.z, gg.w};
                #pragma unroll
                for (int u = 0; u < 4; u++) {
                    int j = jj * 4 + u;
                    float yf = av * gv[u] + db[r * 65 + j];
                    float vv = fmaxf(rstd * (yf - mu * s1v[j]) + s2v[j], 0.f);
                    db[r * 65 + j] = sc[j >> 3] * vv;   // in-place score*value
                }
            }
            __syncthreads();
            // deterministic o reduction over this s-half
            if (tid < 64) {
                float s = 0.f;
                #pragma unroll 8
                for (int rr = 0; rr < 128; rr++) s += db[rr * 65 + tid];
                g_opart[(size_t)(bd * 2 + shalf) * 64 + tid] = s;
            }
            __syncthreads();
        } else {
            float4* orow = (float4*)(outE + (bs * DD + d) * EE);
            #pragma unroll
            for (int jj = 0; jj < 16; jj++) {
                float4 gg = __ldg((const float4*)(G1r + 128) + jj);
                float gv[4] = {gg.x, gg.y, gg.z, gg.w};
                float o4[4];
                #pragma unroll
                for (int u = 0; u < 4; u++) {
                    int j = jj * 4 + u;
                    float y = av * gv[u] + db[r * 65 + j] + av * wds[j] + bes[j];
                    o4[u] = fmaxf(y, 0.f);
                }
                orow[jj] = make_float4(o4[0], o4[1], o4[2], o4[3]);
            }
        }
    }
}

// ---------------- finalize: V_dst_out = V_dst + relu(o @ Wo + bo) ----------------
__global__ void __launch_bounds__(128) fin_kernel(
    const float* __restrict__ Vdst, const float* __restrict__ Wo,
    const float* __restrict__ bo, float* __restrict__ outV) {
    __shared__ float os[64];
    int bd = blockIdx.x;
    int tid = threadIdx.x;
    if (tid < 64)
        os[tid] = g_opart[(size_t)bd * 2 * 64 + tid]
                + g_opart[(size_t)(bd * 2 + 1) * 64 + tid];
    __syncthreads();
    float a = bo[tid];
    #pragma unroll 4
    for (int t = 0; t < 64; t++) a += os[t] * __ldg(Wo + t * VV + tid);
    outV[bd * VV + tid] = Vdst[bd * VV + tid] + fmaxf(a, 0.f);
}

// ---------------- launch ----------------
extern "C" void kernel_launch(void* const* d_in, const int* in_sizes, int n_in,
                              void* d_out, int out_size) {
    const float* V_src = (const float*)d_in[0];
    const float* V_dst = (const float*)d_in[1];
    const float* E     = (const float*)d_in[2];
    const float* A     = (const float*)d_in[3];
    const float* g_vd  = (const float*)d_in[4];
    const float* b_vd  = (const float*)d_in[5];
    const float* g_in  = (const float*)d_in[6];
    const float* b_in  = (const float*)d_in[7];
    const float* Wq    = (const float*)d_in[8];
    const float* bq    = (const float*)d_in[9];
    const float* Wk    = (const float*)d_in[10];
    const float* bk    = (const float*)d_in[11];
    const float* Wv    = (const float*)d_in[12];
    const float* bv    = (const float*)d_in[13];
    const float* Wo    = (const float*)d_in[14];
    const float* bo    = (const float*)d_in[15];
    const float* We    = (const float*)d_in[16];
    const float* be    = (const float*)d_in[17];
    // d_in[18] = Wa, d_in[19] = ba: unused — softmax over singleton axis is exactly 1.

    float* outV = (float*)d_out;                       // [4,256,128]
    float* outE = outV + BB * DD * VV;                 // [4,256,256,64]
    float* outA = outE + (size_t)BB * SS * DD * EE;    // [4,256,256]

    const int SMEM_G1 = (1024 + 64 * 192) * (int)sizeof(float);
    cudaFuncSetAttribute(main_kernel, cudaFuncAttributeMaxDynamicSharedMemorySize, SMEM_MAIN);
    cudaFuncSetAttribute(g1_kernel, cudaFuncAttributeMaxDynamicSharedMemorySize, SMEM_G1);

    prep_wall<<<192, 192>>>(g_in, Wk, Wv, We);
    prep_sums<<<1, 128>>>(g_in, b_in, Wk, bk, Wv, bv);
    prep_wt<<<192, 64>>>();
    g1_kernel<<<BB * SS / 8, 128, SMEM_G1>>>(V_src);
    qwd_kernel<<<BB * DD, 128>>>(V_dst, g_vd, b_vd, Wq, bq, We);
    fill_a<<<(BB * SS * DD) / 1024, 1024>>>(outA);
    main_kernel<<<BB * DD * 2, 128, SMEM_MAIN>>>(E, A, be, outE);
    fin_kernel<<<BB * DD, 128>>>(V_dst, Wo, bo, outV);
}

// round 7
// speedup vs baseline: 1.2051x; 1.2051x over previous
#include <cuda_runtime.h>
#include <cuda_bf16.h>
#include <math.h>
#include <stdint.h>

// Problem constants
#define BB 4
#define SS 256
#define DD 256
#define VV 128
#define EE 64
#define CC 192
#define LN_EPS 1e-3f

// main-kernel smem byte offsets
// W hi/lo: [192 n][72 k] bf16 each (27648 B each)
// X hi/lo: [256 r][72 k] bf16 each (36864 B each) — ALIASED with db after fragments load
#define WH_OFF 0
#define WL_OFF 27648
#define XH_OFF 55296
#define XL_OFF 92160
#define DB_OFF 55296            // [256][65] f32 = 66560 B, aliases X region
#define AUX    129024
#define OFF_QS   (AUX)
#define OFF_WDS  (AUX + 256)
#define OFF_S1K  (AUX + 512)
#define OFF_S2K  (AUX + 768)
#define OFF_S1V  (AUX + 1024)
#define OFF_S2V  (AUX + 1280)
#define OFF_BES  (AUX + 1536)
#define OFF_RED  (AUX + 1792)   // 1024 B
#define SMEM_MAIN (AUX + 1792 + 1024)   // 131840 bytes

// ---------------- device scratch ----------------
__device__ __align__(16) float g_Wall[CC * 192];
__device__ float g_S1k[64], g_S2k[64], g_S1v[64], g_S2v[64];
__device__ float g_q[BB * DD * 64];
__device__ float g_wd[BB * DD * 64];
__device__ float g_o[BB * DD * 64];
__device__ __align__(16) float g_G1[BB * SS * 192];
__device__ float g_sv[BB * SS], g_sq[BB * SS];
__device__ __align__(16) __nv_bfloat16 g_WTh[192 * 72];  // W2^T hi, [n][k] padded
__device__ __align__(16) __nv_bfloat16 g_WTl[192 * 72];  // W2^T lo

// ---------------- mma.sync helper (baseline sm_80+ PTX) ----------------
__device__ __forceinline__ void mma16816(float* c, const uint32_t* a, const uint32_t* b) {
    asm volatile(
        "mma.sync.aligned.m16n8k16.row.col.f32.bf16.bf16.f32 "
        "{%0,%1,%2,%3}, {%4,%5,%6,%7}, {%8,%9}, {%0,%1,%2,%3};"
        : "+f"(c[0]), "+f"(c[1]), "+f"(c[2]), "+f"(c[3])
        : "r"(a[0]), "r"(a[1]), "r"(a[2]), "r"(a[3]), "r"(b[0]), "r"(b[1]));
}

// ---------------- prep: build fused weight matrix ----------------
__global__ void prep_wall(const float* __restrict__ g_in, const float* __restrict__ Wk,
                          const float* __restrict__ Wv, const float* __restrict__ We) {
    int c = blockIdx.x;     // 0..191
    int j = threadIdx.x;    // 0..191
    float g = g_in[c];
    float val;
    if (j < 64)        val = g * Wk[c * 64 + j];
    else if (j < 128)  val = g * Wv[c * 64 + (j - 64)];
    else {
        int t = j - 128;
        val = (c < 128) ? We[c * 64 + t] : We[(c + 128) * 64 + t];
    }
    g_Wall[c * 192 + j] = val;
}

__global__ void prep_sums(const float* __restrict__ g_in, const float* __restrict__ b_in,
                          const float* __restrict__ Wk, const float* __restrict__ bk,
                          const float* __restrict__ Wv, const float* __restrict__ bv) {
    int tid = threadIdx.x;  // 128 threads
    if (tid < 64) {
        int j = tid;
        float s1 = 0.f, s2 = 0.f;
        for (int c = 0; c < CC; c++) {
            float w = Wk[c * 64 + j];
            s1 += g_in[c] * w;
            s2 += b_in[c] * w;
        }
        g_S1k[j] = s1;
        g_S2k[j] = s2 + bk[j];
    } else {
        int j = tid - 64;
        float s1 = 0.f, s2 = 0.f;
        for (int c = 0; c < CC; c++) {
            float w = Wv[c * 64 + j];
            s1 += g_in[c] * w;
            s2 += b_in[c] * w;
        }
        g_S1v[j] = s1;
        g_S2v[j] = s2 + bv[j];
    }
}

// ---------------- prep: bf16 hi/lo image of W2^T [192 n][72 pad k] ----------------
__global__ void prep_wt() {
    int n = blockIdx.x;     // 0..191
    int k = threadIdx.x;    // 0..63
    float w = g_Wall[(128 + k) * 192 + n];
    __nv_bfloat16 wh = __float2bfloat16(w);
    __nv_bfloat16 wl = __float2bfloat16(w - __bfloat162float(wh));
    g_WTh[n * 72 + k] = wh;
    g_WTl[n * 72 + k] = wl;
    if (k >= 56) {  // zero pad tail
        g_WTh[n * 72 + 8 + k] = __float2bfloat16(0.f);
        g_WTl[n * 72 + 8 + k] = __float2bfloat16(0.f);
    }
}

// ---------------- G1 = Vsrc @ Wall[0:128,:]  (+ row sums for LN) ----------------
// 256 threads, 8 s-rows per block, 128 blocks.
__global__ void __launch_bounds__(256) g1_kernel(const float* __restrict__ Vsrc) {
    extern __shared__ float smf[];
    float* xt = smf;           // [128 c][8 r]
    float* ws = smf + 1024;    // [64 c][192 n]
    int bs0 = blockIdx.x * 8;
    int tid = threadIdx.x;
    int tx = tid & 31, ty = tid >> 5;   // ty = row 0..7, tx -> 6 cols (tx + 32i)

    for (int idx = tid; idx < 1024; idx += 256) {
        int c = idx & 127, r = idx >> 7;
        xt[c * 8 + r] = Vsrc[(bs0 + r) * VV + c];
    }
    __syncthreads();
    if (tid < 8) {
        float s = 0.f, ss = 0.f;
        for (int c = 0; c < VV; c++) {
            float x = xt[c * 8 + tid];
            s += x; ss += x * x;
        }
        g_sv[bs0 + tid] = s;
        g_sq[bs0 + tid] = ss;
    }

    float acc[6];
    #pragma unroll
    for (int i = 0; i < 6; i++) acc[i] = 0.f;

    for (int h = 0; h < 2; h++) {
        __syncthreads();
        const float4* src = (const float4*)(g_Wall + h * 64 * 192);
        float4* dst = (float4*)ws;
        for (int idx = tid; idx < 3072; idx += 256) dst[idx] = src[idx];
        __syncthreads();
        #pragma unroll 4
        for (int c = 0; c < 64; c++) {
            float x = xt[(h * 64 + c) * 8 + ty];
            const float* wr = ws + c * 192 + tx;
            #pragma unroll
            for (int i = 0; i < 6; i++) acc[i] = fmaf(x, wr[i * 32], acc[i]);
        }
    }
    float* gout = g_G1 + (size_t)(bs0 + ty) * 192 + tx;
    #pragma unroll
    for (int i = 0; i < 6; i++) gout[i * 32] = acc[i];
}

// ---------------- per-(b,d): LN(V_dst) -> q, and wd GEMV ----------------
__global__ void __launch_bounds__(128) qwd_kernel(
    const float* __restrict__ Vdst, const float* __restrict__ g_vd,
    const float* __restrict__ b_vd, const float* __restrict__ Wq,
    const float* __restrict__ bq, const float* __restrict__ We) {
    __shared__ float vrow[VV];
    __shared__ float vn[VV];
    __shared__ float rsum[4], rsq[4];
    __shared__ float smu, srstd;

    int bd = blockIdx.x;
    int tid = threadIdx.x;
    float x = Vdst[bd * VV + tid];
    vrow[tid] = x;

    float s = x, ss = x * x;
    for (int o = 16; o; o >>= 1) {
        s  += __shfl_down_sync(0xffffffffu, s, o);
        ss += __shfl_down_sync(0xffffffffu, ss, o);
    }
    if ((tid & 31) == 0) { rsum[tid >> 5] = s; rsq[tid >> 5] = ss; }
    __syncthreads();
    if (tid == 0) {
        float S = rsum[0] + rsum[1] + rsum[2] + rsum[3];
        float Q = rsq[0] + rsq[1] + rsq[2] + rsq[3];
        float m = S * (1.f / VV);
        float var = Q * (1.f / VV) - m * m;
        smu = m;
        srstd = rsqrtf(var + LN_EPS);
    }
    __syncthreads();
    vn[tid] = (x - smu) * srstd * g_vd[tid] + b_vd[tid];
    __syncthreads();

    if (tid < 64) {
        float q = bq[tid];
        #pragma unroll 4
        for (int j = 0; j < VV; j++) q += vn[j] * Wq[j * 64 + tid];
        g_q[bd * 64 + tid] = fmaxf(q, 0.f);
    } else {
        int t = tid - 64;
        float w = 0.f;
        #pragma unroll 4
        for (int j = 0; j < VV; j++) w += vrow[j] * We[(128 + j) * 64 + t];
        g_wd[bd * 64 + t] = w;
    }
}

// ---------------- A_new == 1.0 exactly ----------------
__global__ void fill_a(float* __restrict__ outA) {
    int idx = blockIdx.x * 1024 + threadIdx.x;
    outA[idx] = 1.0f;
}

// ---------------- main fused kernel: one (b, d) per block, 256 s-rows ----------------
// D[256,192] = X[256,64] @ W2[64,192] via mma.sync bf16 3-term split, fp32 accum.
__global__ void __launch_bounds__(256) main_kernel(
    const float* __restrict__ Egl, const float* __restrict__ A,
    const float* __restrict__ be, float* __restrict__ outE) {
    extern __shared__ __align__(16) unsigned char smm[];
    int tid = threadIdx.x;
    int lane = tid & 31, wid = tid >> 5;     // 8 warps
    int bx = blockIdx.x;
    int d = bx & 255, b = bx >> 8;
    int bd = b * DD + d;

    float* qs  = (float*)(smm + OFF_QS);
    float* wds = (float*)(smm + OFF_WDS);
    float* s1k = (float*)(smm + OFF_S1K);
    float* s2k = (float*)(smm + OFF_S2K);
    float* s1v = (float*)(smm + OFF_S1V);
    float* s2v = (float*)(smm + OFF_S2V);
    float* bes = (float*)(smm + OFF_BES);
    float* red = (float*)(smm + OFF_RED);
    float* db  = (float*)(smm + DB_OFF);
    if (tid < 64) {
        qs[tid]  = g_q[bd * 64 + tid];
        wds[tid] = g_wd[bd * 64 + tid];
        s1k[tid] = g_S1k[tid]; s2k[tid] = g_S2k[tid];
        s1v[tid] = g_S1v[tid]; s2v[tid] = g_S2v[tid];
        bes[tid] = be[tid];
    }

    // stage W2^T hi/lo into smem
    {
        const uint4* sh = (const uint4*)g_WTh;
        const uint4* sl = (const uint4*)g_WTl;
        uint4* dh = (uint4*)(smm + WH_OFF);
        uint4* dl = (uint4*)(smm + WL_OFF);
        #pragma unroll 4
        for (int i = tid; i < 1728; i += 256) { dh[i] = sh[i]; dl[i] = sl[i]; }
    }

    // per-thread: load E row r (s = r), split to bf16 hi/lo into padded smem; row sums
    int r = tid;
    size_t bs = (size_t)(b * SS + r);
    const float4* ep = (const float4*)(Egl + (bs * DD + d) * EE);
    float se = 0.f, sq = 0.f;
    #pragma unroll
    for (int i = 0; i < 8; i++) {
        float4 u0 = __ldg(ep + 2 * i), u1 = __ldg(ep + 2 * i + 1);
        float x[8] = {u0.x, u0.y, u0.z, u0.w, u1.x, u1.y, u1.z, u1.w};
        #pragma unroll
        for (int t = 0; t < 4; t++) {
            float a0 = x[2 * t], a1 = x[2 * t + 1];
            se += a0 + a1; sq += a0 * a0 + a1 * a1;
            __nv_bfloat16 h0 = __float2bfloat16(a0), h1 = __float2bfloat16(a1);
            __nv_bfloat16 l0 = __float2bfloat16(a0 - __bfloat162float(h0));
            __nv_bfloat16 l1 = __float2bfloat16(a1 - __bfloat162float(h1));
            __nv_bfloat162 ph; ph.x = h0; ph.y = h1;
            __nv_bfloat162 pl; pl.x = l0; pl.y = l1;
            int col = i * 8 + t * 2;
            *(uint32_t*)(smm + XH_OFF + (r * 72 + col) * 2) = *(uint32_t*)&ph;
            *(uint32_t*)(smm + XL_OFF + (r * 72 + col) * 2) = *(uint32_t*)&pl;
        }
    }
    float av = __ldg(A + bs * DD + d);
    float mu = (av * g_sv[bs] + se) * (1.f / CC);
    float msq = (av * av * g_sq[bs] + sq) * (1.f / CC);
    float rstd = rsqrtf(msq - mu * mu + LN_EPS);
    __syncthreads();

    // ---- load A fragments once (rows = wid*32 + mt*16 + {g, g+8}) ----
    int g = lane >> 2, tc = lane & 3;
    uint32_t ahf[2][4][4], alf[2][4][4];
    #pragma unroll
    for (int mt = 0; mt < 2; mt++) {
        int r0 = wid * 32 + mt * 16 + g;
        #pragma unroll
        for (int ks = 0; ks < 4; ks++) {
            int c0 = tc * 2 + 16 * ks;
            ahf[mt][ks][0] = *(const uint32_t*)(smm + XH_OFF + (r0 * 72 + c0) * 2);
            ahf[mt][ks][1] = *(const uint32_t*)(smm + XH_OFF + ((r0 + 8) * 72 + c0) * 2);
            ahf[mt][ks][2] = *(const uint32_t*)(smm + XH_OFF + (r0 * 72 + c0 + 8) * 2);
            ahf[mt][ks][3] = *(const uint32_t*)(smm + XH_OFF + ((r0 + 8) * 72 + c0 + 8) * 2);
            alf[mt][ks][0] = *(const uint32_t*)(smm + XL_OFF + (r0 * 72 + c0) * 2);
            alf[mt][ks][1] = *(const uint32_t*)(smm + XL_OFF + ((r0 + 8) * 72 + c0) * 2);
            alf[mt][ks][2] = *(const uint32_t*)(smm + XL_OFF + (r0 * 72 + c0 + 8) * 2);
            alf[mt][ks][3] = *(const uint32_t*)(smm + XL_OFF + ((r0 + 8) * 72 + c0 + 8) * 2);
        }
    }
    __syncthreads();   // X region now dead; db may overwrite it

    const float* G1r = g_G1 + bs * 192;
    float sc[8];
    #pragma unroll
    for (int h = 0; h < 8; h++) sc[h] = 0.f;

    #pragma unroll 1
    for (int p = 0; p < 3; p++) {
        // ---- GEMM phase p: cols p*64 .. p*64+63 into db ----
        #pragma unroll 1
        for (int nt = 0; nt < 8; nt++) {
            int n = p * 64 + nt * 8 + g;
            uint32_t bhf[4][2], blf[4][2];
            #pragma unroll
            for (int ks = 0; ks < 4; ks++) {
                int kk = tc * 2 + 16 * ks;
                bhf[ks][0] = *(const uint32_t*)(smm + WH_OFF + (n * 72 + kk) * 2);
                bhf[ks][1] = *(const uint32_t*)(smm + WH_OFF + (n * 72 + kk + 8) * 2);
                blf[ks][0] = *(const uint32_t*)(smm + WL_OFF + (n * 72 + kk) * 2);
                blf[ks][1] = *(const uint32_t*)(smm + WL_OFF + (n * 72 + kk + 8) * 2);
            }
            float cHH[2][4], cLH[2][4], cHL[2][4];
            #pragma unroll
            for (int mt = 0; mt < 2; mt++)
                #pragma unroll
                for (int i = 0; i < 4; i++) { cHH[mt][i] = 0.f; cLH[mt][i] = 0.f; cHL[mt][i] = 0.f; }
            #pragma unroll
            for (int ks = 0; ks < 4; ks++) {
                #pragma unroll
                for (int mt = 0; mt < 2; mt++) {
                    mma16816(cHH[mt], ahf[mt][ks], bhf[ks]);
                    mma16816(cLH[mt], alf[mt][ks], bhf[ks]);
                    mma16816(cHL[mt], ahf[mt][ks], blf[ks]);
                }
            }
            #pragma unroll
            for (int mt = 0; mt < 2; mt++) {
                int r0 = wid * 32 + mt * 16 + g;
                int col = nt * 8 + tc * 2;
                db[r0 * 65 + col]           = cHH[mt][0] + cLH[mt][0] + cHL[mt][0];
                db[r0 * 65 + col + 1]       = cHH[mt][1] + cLH[mt][1] + cHL[mt][1];
                db[(r0 + 8) * 65 + col]     = cHH[mt][2] + cLH[mt][2] + cHL[mt][2];
                db[(r0 + 8) * 65 + col + 1] = cHH[mt][3] + cLH[mt][3] + cHL[mt][3];
            }
        }
        __syncthreads();

        // ---- epilogue phase p (per-thread row r) ----
        if (p == 0) {
            #pragma unroll
            for (int jj = 0; jj < 16; jj++) {
                float4 gg = __ldg((const float4*)G1r + jj);
                float gv[4] = {gg.x, gg.y, gg.z, gg.w};
                #pragma unroll
                for (int u = 0; u < 4; u++) {
                    int j = jj * 4 + u;
                    float yf = av * gv[u] + db[r * 65 + j];
                    float kk = fmaxf(rstd * (yf - mu * s1k[j]) + s2k[j], 0.f);
                    sc[j >> 3] += qs[j] * kk;
                }
            }
            float mx = sc[0] * 0.35355339059327373f;
            #pragma unroll
            for (int h = 0; h < 8; h++) { sc[h] *= 0.35355339059327373f; mx = fmaxf(mx, sc[h]); }
            float sum = 0.f;
            #pragma unroll
            for (int h = 0; h < 8; h++) { sc[h] = __expf(sc[h] - mx); sum += sc[h]; }
            float inv = 1.f / sum;
            #pragma unroll
            for (int h = 0; h < 8; h++) sc[h] *= inv;
            __syncthreads();
        } else if (p == 1) {
            #pragma unroll
            for (int jj = 0; jj < 16; jj++) {
                float4 gg = __ldg((const float4*)(G1r + 64) + jj);
                float gv[4] = {gg.x, gg.y, gg.z, gg.w};
                #pragma unroll
                for (int u = 0; u < 4; u++) {
                    int j = jj * 4 + u;
                    float yf = av * gv[u] + db[r * 65 + j];
                    float vv = fmaxf(rstd * (yf - mu * s1v[j]) + s2v[j], 0.f);
                    db[r * 65 + j] = sc[j >> 3] * vv;   // in-place score*value
                }
            }
            __syncthreads();
            // deterministic o reduction: 4 partials of 64 rows each, fixed combine
            {
                int col = tid & 63, q = tid >> 6;
                float s = 0.f;
                int rr0 = q * 64;
                #pragma unroll 8
                for (int rr = rr0; rr < rr0 + 64; rr++) s += db[rr * 65 + col];
                red[q * 64 + col] = s;
            }
            __syncthreads();
            if (tid < 64) {
                float s = (red[tid] + red[64 + tid]) + (red[128 + tid] + red[192 + tid]);
                g_o[(size_t)bd * 64 + tid] = s;
            }
            __syncthreads();
        } else {
            float4* orow = (float4*)(outE + (bs * DD + d) * EE);
            #pragma unroll
            for (int jj = 0; jj < 16; jj++) {
                float4 gg = __ldg((const float4*)(G1r + 128) + jj);
                float gv[4] = {gg.x, gg.y, gg.z, gg.w};
                float o4[4];
                #pragma unroll
                for (int u = 0; u < 4; u++) {
                    int j = jj * 4 + u;
                    float y = av * gv[u] + db[r * 65 + j] + av * wds[j] + bes[j];
                    o4[u] = fmaxf(y, 0.f);
                }
                orow[jj] = make_float4(o4[0], o4[1], o4[2], o4[3]);
            }
        }
    }
}

// ---------------- finalize: V_dst_out = V_dst + relu(o @ Wo + bo) ----------------
__global__ void __launch_bounds__(128) fin_kernel(
    const float* __restrict__ Vdst, const float* __restrict__ Wo,
    const float* __restrict__ bo, float* __restrict__ outV) {
    __shared__ float os[64];
    int bd = blockIdx.x;
    int tid = threadIdx.x;
    if (tid < 64) os[tid] = g_o[(size_t)bd * 64 + tid];
    __syncthreads();
    float a = bo[tid];
    #pragma unroll 4
    for (int t = 0; t < 64; t++) a += os[t] * __ldg(Wo + t * VV + tid);
    outV[bd * VV + tid] = Vdst[bd * VV + tid] + fmaxf(a, 0.f);
}

// ---------------- launch ----------------
extern "C" void kernel_launch(void* const* d_in, const int* in_sizes, int n_in,
                              void* d_out, int out_size) {
    const float* V_src = (const float*)d_in[0];
    const float* V_dst = (const float*)d_in[1];
    const float* E     = (const float*)d_in[2];
    const float* A     = (const float*)d_in[3];
    const float* g_vd  = (const float*)d_in[4];
    const float* b_vd  = (const float*)d_in[5];
    const float* g_in  = (const float*)d_in[6];
    const float* b_in  = (const float*)d_in[7];
    const float* Wq    = (const float*)d_in[8];
    const float* bq    = (const float*)d_in[9];
    const float* Wk    = (const float*)d_in[10];
    const float* bk    = (const float*)d_in[11];
    const float* Wv    = (const float*)d_in[12];
    const float* bv    = (const float*)d_in[13];
    const float* Wo    = (const float*)d_in[14];
    const float* bo    = (const float*)d_in[15];
    const float* We    = (const float*)d_in[16];
    const float* be    = (const float*)d_in[17];
    // d_in[18] = Wa, d_in[19] = ba: unused — softmax over singleton axis is exactly 1.

    float* outV = (float*)d_out;                       // [4,256,128]
    float* outE = outV + BB * DD * VV;                 // [4,256,256,64]
    float* outA = outE + (size_t)BB * SS * DD * EE;    // [4,256,256]

    const int SMEM_G1 = (1024 + 64 * 192) * (int)sizeof(float);
    cudaFuncSetAttribute(main_kernel, cudaFuncAttributeMaxDynamicSharedMemorySize, SMEM_MAIN);
    cudaFuncSetAttribute(g1_kernel, cudaFuncAttributeMaxDynamicSharedMemorySize, SMEM_G1);

    prep_wall<<<192, 192>>>(g_in, Wk, Wv, We);
    prep_sums<<<1, 128>>>(g_in, b_in, Wk, bk, Wv, bv);
    prep_wt<<<192, 64>>>();
    g1_kernel<<<BB * SS / 8, 256, SMEM_G1>>>(V_src);
    qwd_kernel<<<BB * DD, 128>>>(V_dst, g_vd, b_vd, Wq, bq, We);
    fill_a<<<(BB * SS * DD) / 1024, 1024>>>(outA);
    main_kernel<<<BB * DD, 256, SMEM_MAIN>>>(E, A, be, outE);
    fin_kernel<<<BB * DD, 128>>>(V_dst, Wo, bo, outV);
}

// round 8
// speedup vs baseline: 1.3289x; 1.1027x over previous
#include <cuda_runtime.h>
#include <cuda_bf16.h>
#include <math.h>
#include <stdint.h>

// Problem constants
#define BB 4
#define SS 256
#define DD 256
#define VV 128
#define EE 64
#define CC 192
#define LN_EPS 1e-3f

// main-kernel smem byte offsets
// W hi/lo: [192 n][72 k] bf16 each (27648 B each)
// DBX region: X chunk hi/lo (2 x 9216 B, transient) aliased under db [256][33] f32 (33792 B)
#define WH_OFF  0
#define WL_OFF  27648
#define DBX_OFF 55296
#define XH_OFF  DBX_OFF
#define XL_OFF  (DBX_OFF + 9216)
#define AUX     89088
#define OFF_QS   (AUX)
#define OFF_WDS  (AUX + 256)
#define OFF_S1K  (AUX + 512)
#define OFF_S2K  (AUX + 768)
#define OFF_S1V  (AUX + 1024)
#define OFF_S2V  (AUX + 1280)
#define OFF_BES  (AUX + 1536)
#define OFF_SSUM (AUX + 1792)
#define OFF_SSQ  (AUX + 2816)
#define OFF_RED  (AUX + 3840)
#define SMEM_MAIN (AUX + 4864)   // 93952 bytes -> 2 CTAs/SM

// ---------------- device scratch ----------------
__device__ __align__(16) float g_Wall[CC * 192];
__device__ float g_S1k[64], g_S2k[64], g_S1v[64], g_S2v[64];
__device__ float g_q[BB * DD * 64];
__device__ float g_wd[BB * DD * 64];
__device__ float g_o[BB * DD * 64];
__device__ __align__(16) float g_G1[BB * SS * 192];
__device__ float g_sv[BB * SS], g_sq[BB * SS];
__device__ __align__(16) __nv_bfloat16 g_WTh[192 * 72];  // W2^T hi, [n][k] padded
__device__ __align__(16) __nv_bfloat16 g_WTl[192 * 72];  // W2^T lo

// ---------------- mma.sync helper (baseline sm_80+ PTX) ----------------
__device__ __forceinline__ void mma16816(float* c, const uint32_t* a, const uint32_t* b) {
    asm volatile(
        "mma.sync.aligned.m16n8k16.row.col.f32.bf16.bf16.f32 "
        "{%0,%1,%2,%3}, {%4,%5,%6,%7}, {%8,%9}, {%0,%1,%2,%3};"
        : "+f"(c[0]), "+f"(c[1]), "+f"(c[2]), "+f"(c[3])
        : "r"(a[0]), "r"(a[1]), "r"(a[2]), "r"(a[3]), "r"(b[0]), "r"(b[1]));
}

// ---------------- prep: build fused weight matrix ----------------
__global__ void prep_wall(const float* __restrict__ g_in, const float* __restrict__ Wk,
                          const float* __restrict__ Wv, const float* __restrict__ We) {
    int c = blockIdx.x;     // 0..191
    int j = threadIdx.x;    // 0..191
    float g = g_in[c];
    float val;
    if (j < 64)        val = g * Wk[c * 64 + j];
    else if (j < 128)  val = g * Wv[c * 64 + (j - 64)];
    else {
        int t = j - 128;
        val = (c < 128) ? We[c * 64 + t] : We[(c + 128) * 64 + t];
    }
    g_Wall[c * 192 + j] = val;
}

__global__ void prep_sums(const float* __restrict__ g_in, const float* __restrict__ b_in,
                          const float* __restrict__ Wk, const float* __restrict__ bk,
                          const float* __restrict__ Wv, const float* __restrict__ bv) {
    int tid = threadIdx.x;  // 128 threads
    if (tid < 64) {
        int j = tid;
        float s1 = 0.f, s2 = 0.f;
        for (int c = 0; c < CC; c++) {
            float w = Wk[c * 64 + j];
            s1 += g_in[c] * w;
            s2 += b_in[c] * w;
        }
        g_S1k[j] = s1;
        g_S2k[j] = s2 + bk[j];
    } else {
        int j = tid - 64;
        float s1 = 0.f, s2 = 0.f;
        for (int c = 0; c < CC; c++) {
            float w = Wv[c * 64 + j];
            s1 += g_in[c] * w;
            s2 += b_in[c] * w;
        }
        g_S1v[j] = s1;
        g_S2v[j] = s2 + bv[j];
    }
}

// ---------------- prep: bf16 hi/lo image of W2^T [192 n][72 pad k] ----------------
__global__ void prep_wt() {
    int n = blockIdx.x;     // 0..191
    int k = threadIdx.x;    // 0..63
    float w = g_Wall[(128 + k) * 192 + n];
    __nv_bfloat16 wh = __float2bfloat16(w);
    __nv_bfloat16 wl = __float2bfloat16(w - __bfloat162float(wh));
    g_WTh[n * 72 + k] = wh;
    g_WTl[n * 72 + k] = wl;
    if (k >= 56) {  // zero pad tail
        g_WTh[n * 72 + 8 + k] = __float2bfloat16(0.f);
        g_WTl[n * 72 + 8 + k] = __float2bfloat16(0.f);
    }
}

// ---------------- G1 = Vsrc @ Wall[0:128,:]  (+ row sums for LN) ----------------
__global__ void __launch_bounds__(256) g1_kernel(const float* __restrict__ Vsrc) {
    extern __shared__ float smf[];
    float* xt = smf;           // [128 c][8 r]
    float* ws = smf + 1024;    // [64 c][192 n]
    int bs0 = blockIdx.x * 8;
    int tid = threadIdx.x;
    int tx = tid & 31, ty = tid >> 5;

    for (int idx = tid; idx < 1024; idx += 256) {
        int c = idx & 127, r = idx >> 7;
        xt[c * 8 + r] = Vsrc[(bs0 + r) * VV + c];
    }
    __syncthreads();
    if (tid < 8) {
        float s = 0.f, ss = 0.f;
        for (int c = 0; c < VV; c++) {
            float x = xt[c * 8 + tid];
            s += x; ss += x * x;
        }
        g_sv[bs0 + tid] = s;
        g_sq[bs0 + tid] = ss;
    }

    float acc[6];
    #pragma unroll
    for (int i = 0; i < 6; i++) acc[i] = 0.f;

    for (int h = 0; h < 2; h++) {
        __syncthreads();
        const float4* src = (const float4*)(g_Wall + h * 64 * 192);
        float4* dst = (float4*)ws;
        for (int idx = tid; idx < 3072; idx += 256) dst[idx] = src[idx];
        __syncthreads();
        #pragma unroll 4
        for (int c = 0; c < 64; c++) {
            float x = xt[(h * 64 + c) * 8 + ty];
            const float* wr = ws + c * 192 + tx;
            #pragma unroll
            for (int i = 0; i < 6; i++) acc[i] = fmaf(x, wr[i * 32], acc[i]);
        }
    }
    float* gout = g_G1 + (size_t)(bs0 + ty) * 192 + tx;
    #pragma unroll
    for (int i = 0; i < 6; i++) gout[i * 32] = acc[i];
}

// ---------------- per-(b,d): LN(V_dst) -> q, and wd GEMV ----------------
__global__ void __launch_bounds__(128) qwd_kernel(
    const float* __restrict__ Vdst, const float* __restrict__ g_vd,
    const float* __restrict__ b_vd, const float* __restrict__ Wq,
    const float* __restrict__ bq, const float* __restrict__ We) {
    __shared__ float vrow[VV];
    __shared__ float vn[VV];
    __shared__ float rsum[4], rsq[4];
    __shared__ float smu, srstd;

    int bd = blockIdx.x;
    int tid = threadIdx.x;
    float x = Vdst[bd * VV + tid];
    vrow[tid] = x;

    float s = x, ss = x * x;
    for (int o = 16; o; o >>= 1) {
        s  += __shfl_down_sync(0xffffffffu, s, o);
        ss += __shfl_down_sync(0xffffffffu, ss, o);
    }
    if ((tid & 31) == 0) { rsum[tid >> 5] = s; rsq[tid >> 5] = ss; }
    __syncthreads();
    if (tid == 0) {
        float S = rsum[0] + rsum[1] + rsum[2] + rsum[3];
        float Q = rsq[0] + rsq[1] + rsq[2] + rsq[3];
        float m = S * (1.f / VV);
        float var = Q * (1.f / VV) - m * m;
        smu = m;
        srstd = rsqrtf(var + LN_EPS);
    }
    __syncthreads();
    vn[tid] = (x - smu) * srstd * g_vd[tid] + b_vd[tid];
    __syncthreads();

    if (tid < 64) {
        float q = bq[tid];
        #pragma unroll 4
        for (int j = 0; j < VV; j++) q += vn[j] * Wq[j * 64 + tid];
        g_q[bd * 64 + tid] = fmaxf(q, 0.f);
    } else {
        int t = tid - 64;
        float w = 0.f;
        #pragma unroll 4
        for (int j = 0; j < VV; j++) w += vrow[j] * We[(128 + j) * 64 + t];
        g_wd[bd * 64 + t] = w;
    }
}

// ---------------- A_new == 1.0 exactly ----------------
__global__ void fill_a(float* __restrict__ outA) {
    int idx = blockIdx.x * 1024 + threadIdx.x;
    outA[idx] = 1.0f;
}

// ---------------- main fused kernel: one (b, d) per block, 256 s-rows, 2 CTAs/SM ----------------
__global__ void __launch_bounds__(256, 2) main_kernel(
    const float* __restrict__ Egl, const float* __restrict__ A,
    const float* __restrict__ be, float* __restrict__ outE) {
    extern __shared__ __align__(16) unsigned char smm[];
    int tid = threadIdx.x;
    int lane = tid & 31, wid = tid >> 5;     // 8 warps
    int bx = blockIdx.x;
    int d = bx & 255, b = bx >> 8;
    int bd = b * DD + d;

    float* qs   = (float*)(smm + OFF_QS);
    float* wds  = (float*)(smm + OFF_WDS);
    float* s1k  = (float*)(smm + OFF_S1K);
    float* s2k  = (float*)(smm + OFF_S2K);
    float* s1v  = (float*)(smm + OFF_S1V);
    float* s2v  = (float*)(smm + OFF_S2V);
    float* bes  = (float*)(smm + OFF_BES);
    float* ssum = (float*)(smm + OFF_SSUM);
    float* ssq  = (float*)(smm + OFF_SSQ);
    float* red  = (float*)(smm + OFF_RED);
    float* db   = (float*)(smm + DBX_OFF);
    if (tid < 64) {
        qs[tid]  = g_q[bd * 64 + tid];
        wds[tid] = g_wd[bd * 64 + tid];
        s1k[tid] = g_S1k[tid]; s2k[tid] = g_S2k[tid];
        s1v[tid] = g_S1v[tid]; s2v[tid] = g_S2v[tid];
        bes[tid] = be[tid];
    }

    // stage W2^T hi/lo into smem (needed only at GEMM time; syncs below cover)
    {
        const uint4* sh = (const uint4*)g_WTh;
        const uint4* sl = (const uint4*)g_WTl;
        uint4* dh = (uint4*)(smm + WH_OFF);
        uint4* dl = (uint4*)(smm + WL_OFF);
        #pragma unroll 4
        for (int i = tid; i < 1728; i += 256) { dh[i] = sh[i]; dl[i] = sl[i]; }
    }

    // ---- chunked X staging (coalesced) + per-chunk fragment pickup ----
    int g = lane >> 2, tc = lane & 3;
    uint32_t ahf[2][4][4], alf[2][4][4];
    int mychunk = wid >> 1;
    #pragma unroll 1
    for (int c = 0; c < 4; c++) {
        #pragma unroll
        for (int it = 0; it < 4; it++) {
            int idx = it * 256 + tid;        // 0..1023
            int lrow = idx >> 4;             // 0..63
            int seg = idx & 15;              // 0..15
            int row = c * 64 + lrow;
            float4 u = __ldg((const float4*)(Egl + ((size_t)(b * SS + row) * DD + d) * EE) + seg);
            float ps = u.x + u.y + u.z + u.w;
            float pq = u.x * u.x + u.y * u.y + u.z * u.z + u.w * u.w;
            #pragma unroll
            for (int o = 8; o; o >>= 1) {
                ps += __shfl_xor_sync(0xffffffffu, ps, o);
                pq += __shfl_xor_sync(0xffffffffu, pq, o);
            }
            if ((lane & 15) == 0) { ssum[row] = ps; ssq[row] = pq; }
            float x[4] = {u.x, u.y, u.z, u.w};
            uint32_t hp[2], lp[2];
            #pragma unroll
            for (int t = 0; t < 2; t++) {
                float a0 = x[2 * t], a1 = x[2 * t + 1];
                __nv_bfloat16 h0 = __float2bfloat16(a0), h1 = __float2bfloat16(a1);
                __nv_bfloat16 l0 = __float2bfloat16(a0 - __bfloat162float(h0));
                __nv_bfloat16 l1 = __float2bfloat16(a1 - __bfloat162float(h1));
                __nv_bfloat162 ph; ph.x = h0; ph.y = h1;
                __nv_bfloat162 pl; pl.x = l0; pl.y = l1;
                hp[t] = *(uint32_t*)&ph; lp[t] = *(uint32_t*)&pl;
            }
            uint32_t boff = (uint32_t)(lrow * 72 + seg * 4) * 2;
            *(uint2*)(smm + XH_OFF + boff) = make_uint2(hp[0], hp[1]);
            *(uint2*)(smm + XL_OFF + boff) = make_uint2(lp[0], lp[1]);
        }
        __syncthreads();
        if (mychunk == c) {
            int rb = (wid & 1) * 32 + g;     // local row base within chunk
            #pragma unroll
            for (int mt = 0; mt < 2; mt++) {
                int r0 = rb + mt * 16;
                #pragma unroll
                for (int ks = 0; ks < 4; ks++) {
                    int c0 = tc * 2 + 16 * ks;
                    ahf[mt][ks][0] = *(const uint32_t*)(smm + XH_OFF + (r0 * 72 + c0) * 2);
                    ahf[mt][ks][1] = *(const uint32_t*)(smm + XH_OFF + ((r0 + 8) * 72 + c0) * 2);
                    ahf[mt][ks][2] = *(const uint32_t*)(smm + XH_OFF + (r0 * 72 + c0 + 8) * 2);
                    ahf[mt][ks][3] = *(const uint32_t*)(smm + XH_OFF + ((r0 + 8) * 72 + c0 + 8) * 2);
                    alf[mt][ks][0] = *(const uint32_t*)(smm + XL_OFF + (r0 * 72 + c0) * 2);
                    alf[mt][ks][1] = *(const uint32_t*)(smm + XL_OFF + ((r0 + 8) * 72 + c0) * 2);
                    alf[mt][ks][2] = *(const uint32_t*)(smm + XL_OFF + (r0 * 72 + c0 + 8) * 2);
                    alf[mt][ks][3] = *(const uint32_t*)(smm + XL_OFF + ((r0 + 8) * 72 + c0 + 8) * 2);
                }
            }
        }
        __syncthreads();
    }

    // per-thread row r = tid: LN stats
    int r = tid;
    size_t bs = (size_t)(b * SS + r);
    float av = __ldg(A + bs * DD + d);
    float mu = (av * g_sv[bs] + ssum[r]) * (1.f / CC);
    float msq = (av * av * g_sq[bs] + ssq[r]) * (1.f / CC);
    float rstd = rsqrtf(msq - mu * mu + LN_EPS);

    const float* G1r = g_G1 + bs * 192;
    float sc[8];
    #pragma unroll
    for (int h = 0; h < 8; h++) sc[h] = 0.f;

    // ---- 6 phases of 32 columns each ----
    #pragma unroll 1
    for (int p = 0; p < 6; p++) {
        // GEMM: cols p*32 .. p*32+31 into db[256][33]
        #pragma unroll 1
        for (int nt = 0; nt < 4; nt++) {
            int n = p * 32 + nt * 8 + g;
            uint32_t bhf[4][2], blf[4][2];
            #pragma unroll
            for (int ks = 0; ks < 4; ks++) {
                int kk = tc * 2 + 16 * ks;
                bhf[ks][0] = *(const uint32_t*)(smm + WH_OFF + (n * 72 + kk) * 2);
                bhf[ks][1] = *(const uint32_t*)(smm + WH_OFF + (n * 72 + kk + 8) * 2);
                blf[ks][0] = *(const uint32_t*)(smm + WL_OFF + (n * 72 + kk) * 2);
                blf[ks][1] = *(const uint32_t*)(smm + WL_OFF + (n * 72 + kk + 8) * 2);
            }
            float acc[2][4];
            #pragma unroll
            for (int mt = 0; mt < 2; mt++)
                #pragma unroll
                for (int i = 0; i < 4; i++) acc[mt][i] = 0.f;
            #pragma unroll
            for (int ks = 0; ks < 4; ks++) {
                #pragma unroll
                for (int mt = 0; mt < 2; mt++) {
                    mma16816(acc[mt], ahf[mt][ks], bhf[ks]);
                    mma16816(acc[mt], alf[mt][ks], bhf[ks]);
                    mma16816(acc[mt], ahf[mt][ks], blf[ks]);
                }
            }
            #pragma unroll
            for (int mt = 0; mt < 2; mt++) {
                int r0 = wid * 32 + mt * 16 + g;
                int col = nt * 8 + tc * 2;
                db[r0 * 33 + col]           = acc[mt][0];
                db[r0 * 33 + col + 1]       = acc[mt][1];
                db[(r0 + 8) * 33 + col]     = acc[mt][2];
                db[(r0 + 8) * 33 + col + 1] = acc[mt][3];
            }
        }
        __syncthreads();

        // epilogue
        if (p < 2) {
            const float4* gp = (const float4*)(G1r + p * 32);
            #pragma unroll
            for (int jj = 0; jj < 8; jj++) {
                float4 gg = __ldg(gp + jj);
                float gv[4] = {gg.x, gg.y, gg.z, gg.w};
                #pragma unroll
                for (int u = 0; u < 4; u++) {
                    int j = jj * 4 + u;
                    int jg = p * 32 + j;
                    float yf = av * gv[u] + db[r * 33 + j];
                    float kk = fmaxf(rstd * (yf - mu * s1k[jg]) + s2k[jg], 0.f);
                    sc[jg >> 3] += qs[jg] * kk;
                }
            }
            if (p == 1) {
                float mx = sc[0] * 0.35355339059327373f;
                #pragma unroll
                for (int h = 0; h < 8; h++) { sc[h] *= 0.35355339059327373f; mx = fmaxf(mx, sc[h]); }
                float sum = 0.f;
                #pragma unroll
                for (int h = 0; h < 8; h++) { sc[h] = __expf(sc[h] - mx); sum += sc[h]; }
                float inv = 1.f / sum;
                #pragma unroll
                for (int h = 0; h < 8; h++) sc[h] *= inv;
            }
            __syncthreads();
        } else if (p < 4) {
            int q = p - 2;
            const float4* gp = (const float4*)(G1r + 64 + q * 32);
            #pragma unroll
            for (int jj = 0; jj < 8; jj++) {
                float4 gg = __ldg(gp + jj);
                float gv[4] = {gg.x, gg.y, gg.z, gg.w};
                #pragma unroll
                for (int u = 0; u < 4; u++) {
                    int j = jj * 4 + u;
                    int jg = q * 32 + j;
                    float yf = av * gv[u] + db[r * 33 + j];
                    float vv = fmaxf(rstd * (yf - mu * s1v[jg]) + s2v[jg], 0.f);
                    db[r * 33 + j] = sc[jg >> 3] * vv;
                }
            }
            __syncthreads();
            // deterministic column reduce: 8 partials of 32 rows
            {
                int col = tid & 31, qq = tid >> 5;
                float s = 0.f;
                int rr0 = qq * 32;
                #pragma unroll 8
                for (int rr = rr0; rr < rr0 + 32; rr++) s += db[rr * 33 + col];
                red[qq * 32 + col] = s;
            }
            __syncthreads();
            if (tid < 32) {
                float s = ((red[tid] + red[32 + tid]) + (red[64 + tid] + red[96 + tid]))
                        + ((red[128 + tid] + red[160 + tid]) + (red[192 + tid] + red[224 + tid]));
                g_o[(size_t)bd * 64 + q * 32 + tid] = s;
            }
            __syncthreads();
        } else {
            int q = p - 4;
            const float4* gp = (const float4*)(G1r + 128 + q * 32);
            float4* orow = (float4*)(outE + (bs * DD + d) * EE + q * 32);
            #pragma unroll
            for (int jj = 0; jj < 8; jj++) {
                float4 gg = __ldg(gp + jj);
                float gv[4] = {gg.x, gg.y, gg.z, gg.w};
                float o4[4];
                #pragma unroll
                for (int u = 0; u < 4; u++) {
                    int j = jj * 4 + u;
                    int jg = q * 32 + j;
                    float y = av * gv[u] + db[r * 33 + j] + av * wds[jg] + bes[jg];
                    o4[u] = fmaxf(y, 0.f);
                }
                orow[jj] = make_float4(o4[0], o4[1], o4[2], o4[3]);
            }
            if (p == 4) __syncthreads();
        }
    }
}

// ---------------- finalize: V_dst_out = V_dst + relu(o @ Wo + bo) ----------------
__global__ void __launch_bounds__(128) fin_kernel(
    const float* __restrict__ Vdst, const float* __restrict__ Wo,
    const float* __restrict__ bo, float* __restrict__ outV) {
    __shared__ float os[64];
    int bd = blockIdx.x;
    int tid = threadIdx.x;
    if (tid < 64) os[tid] = g_o[(size_t)bd * 64 + tid];
    __syncthreads();
    float a = bo[tid];
    #pragma unroll 4
    for (int t = 0; t < 64; t++) a += os[t] * __ldg(Wo + t * VV + tid);
    outV[bd * VV + tid] = Vdst[bd * VV + tid] + fmaxf(a, 0.f);
}

// ---------------- launch ----------------
extern "C" void kernel_launch(void* const* d_in, const int* in_sizes, int n_in,
                              void* d_out, int out_size) {
    const float* V_src = (const float*)d_in[0];
    const float* V_dst = (const float*)d_in[1];
    const float* E     = (const float*)d_in[2];
    const float* A     = (const float*)d_in[3];
    const float* g_vd  = (const float*)d_in[4];
    const float* b_vd  = (const float*)d_in[5];
    const float* g_in  = (const float*)d_in[6];
    const float* b_in  = (const float*)d_in[7];
    const float* Wq    = (const float*)d_in[8];
    const float* bq    = (const float*)d_in[9];
    const float* Wk    = (const float*)d_in[10];
    const float* bk    = (const float*)d_in[11];
    const float* Wv    = (const float*)d_in[12];
    const float* bv    = (const float*)d_in[13];
    const float* Wo    = (const float*)d_in[14];
    const float* bo    = (const float*)d_in[15];
    const float* We    = (const float*)d_in[16];
    const float* be    = (const float*)d_in[17];
    // d_in[18] = Wa, d_in[19] = ba: unused — softmax over singleton axis is exactly 1.

    float* outV = (float*)d_out;                       // [4,256,128]
    float* outE = outV + BB * DD * VV;                 // [4,256,256,64]
    float* outA = outE + (size_t)BB * SS * DD * EE;    // [4,256,256]

    const int SMEM_G1 = (1024 + 64 * 192) * (int)sizeof(float);
    cudaFuncSetAttribute(main_kernel, cudaFuncAttributeMaxDynamicSharedMemorySize, SMEM_MAIN);
    cudaFuncSetAttribute(g1_kernel, cudaFuncAttributeMaxDynamicSharedMemorySize, SMEM_G1);

    prep_wall<<<192, 192>>>(g_in, Wk, Wv, We);
    prep_sums<<<1, 128>>>(g_in, b_in, Wk, bk, Wv, bv);
    prep_wt<<<192, 64>>>();
    g1_kernel<<<BB * SS / 8, 256, SMEM_G1>>>(V_src);
    qwd_kernel<<<BB * DD, 128>>>(V_dst, g_vd, b_vd, Wq, bq, We);
    fill_a<<<(BB * SS * DD) / 1024, 1024>>>(outA);
    main_kernel<<<BB * DD, 256, SMEM_MAIN>>>(E, A, be, outE);
    fin_kernel<<<BB * DD, 128>>>(V_dst, Wo, bo, outV);
}

// round 9
// speedup vs baseline: 1.6244x; 1.2223x over previous
#include <cuda_runtime.h>
#include <cuda_bf16.h>
#include <math.h>
#include <stdint.h>

// Problem constants
#define BB 4
#define SS 256
#define DD 256
#define VV 128
#define EE 64
#define CC 192
#define LN_EPS 1e-3f

// main-kernel smem byte offsets
// W hi/lo: [192 n][72 k] bf16 each (27648 B each)
// DBX region: X chunk hi/lo (2 x 9216 B, transient) aliased under db [256][33] f32 (33792 B)
#define WH_OFF  0
#define WL_OFF  27648
#define DBX_OFF 55296
#define XH_OFF  DBX_OFF
#define XL_OFF  (DBX_OFF + 9216)
#define AUX     89088
#define OFF_QS   (AUX)
#define OFF_WDS  (AUX + 256)
#define OFF_S1K  (AUX + 512)
#define OFF_S2K  (AUX + 768)
#define OFF_S1V  (AUX + 1024)
#define OFF_S2V  (AUX + 1280)
#define OFF_BES  (AUX + 1536)
#define OFF_SSUM (AUX + 1792)
#define OFF_SSQ  (AUX + 2816)
#define OFF_RED  (AUX + 3840)
#define SMEM_MAIN (AUX + 4864)   // 93952 bytes -> 2 CTAs/SM

// ---------------- device scratch ----------------
__device__ __align__(16) float g_Wall[CC * 192];
__device__ float g_S1k[64], g_S2k[64], g_S1v[64], g_S2v[64];
__device__ float g_q[BB * DD * 64];
__device__ float g_wd[BB * DD * 64];
__device__ float g_o[BB * DD * 64];
__device__ __align__(16) float g_G1T[192 * BB * SS];  // TRANSPOSED: [n][b*s]
__device__ float g_sv[BB * SS], g_sq[BB * SS];
__device__ __align__(16) __nv_bfloat16 g_WTh[192 * 72];  // W2^T hi, [n][k] padded
__device__ __align__(16) __nv_bfloat16 g_WTl[192 * 72];  // W2^T lo

// ---------------- mma.sync helper (baseline sm_80+ PTX) ----------------
__device__ __forceinline__ void mma16816(float* c, const uint32_t* a, const uint32_t* b) {
    asm volatile(
        "mma.sync.aligned.m16n8k16.row.col.f32.bf16.bf16.f32 "
        "{%0,%1,%2,%3}, {%4,%5,%6,%7}, {%8,%9}, {%0,%1,%2,%3};"
        : "+f"(c[0]), "+f"(c[1]), "+f"(c[2]), "+f"(c[3])
        : "r"(a[0]), "r"(a[1]), "r"(a[2]), "r"(a[3]), "r"(b[0]), "r"(b[1]));
}

// ---------------- prep: build fused weight matrix ----------------
__global__ void prep_wall(const float* __restrict__ g_in, const float* __restrict__ Wk,
                          const float* __restrict__ Wv, const float* __restrict__ We) {
    int c = blockIdx.x;     // 0..191
    int j = threadIdx.x;    // 0..191
    float g = g_in[c];
    float val;
    if (j < 64)        val = g * Wk[c * 64 + j];
    else if (j < 128)  val = g * Wv[c * 64 + (j - 64)];
    else {
        int t = j - 128;
        val = (c < 128) ? We[c * 64 + t] : We[(c + 128) * 64 + t];
    }
    g_Wall[c * 192 + j] = val;
}

__global__ void prep_sums(const float* __restrict__ g_in, const float* __restrict__ b_in,
                          const float* __restrict__ Wk, const float* __restrict__ bk,
                          const float* __restrict__ Wv, const float* __restrict__ bv) {
    int tid = threadIdx.x;  // 128 threads
    if (tid < 64) {
        int j = tid;
        float s1 = 0.f, s2 = 0.f;
        for (int c = 0; c < CC; c++) {
            float w = Wk[c * 64 + j];
            s1 += g_in[c] * w;
            s2 += b_in[c] * w;
        }
        g_S1k[j] = s1;
        g_S2k[j] = s2 + bk[j];
    } else {
        int j = tid - 64;
        float s1 = 0.f, s2 = 0.f;
        for (int c = 0; c < CC; c++) {
            float w = Wv[c * 64 + j];
            s1 += g_in[c] * w;
            s2 += b_in[c] * w;
        }
        g_S1v[j] = s1;
        g_S2v[j] = s2 + bv[j];
    }
}

// ---------------- prep: bf16 hi/lo image of W2^T [192 n][72 pad k] ----------------
__global__ void prep_wt() {
    int n = blockIdx.x;     // 0..191
    int k = threadIdx.x;    // 0..63
    float w = g_Wall[(128 + k) * 192 + n];
    __nv_bfloat16 wh = __float2bfloat16(w);
    __nv_bfloat16 wl = __float2bfloat16(w - __bfloat162float(wh));
    g_WTh[n * 72 + k] = wh;
    g_WTl[n * 72 + k] = wl;
    if (k >= 56) {  // zero pad tail
        g_WTh[n * 72 + 8 + k] = __float2bfloat16(0.f);
        g_WTl[n * 72 + 8 + k] = __float2bfloat16(0.f);
    }
}

// ---------------- G1T[n][bs] = (Vsrc @ Wall[0:128,:])^T  (+ row sums for LN) ----------------
__global__ void __launch_bounds__(256) g1_kernel(const float* __restrict__ Vsrc) {
    extern __shared__ float smf[];
    float* xt = smf;           // [128 c][8 r]
    float* ws = smf + 1024;    // [64 c][192 n]
    int bs0 = blockIdx.x * 8;
    int tid = threadIdx.x;
    int tx = tid & 31, ty = tid >> 5;

    for (int idx = tid; idx < 1024; idx += 256) {
        int c = idx & 127, r = idx >> 7;
        xt[c * 8 + r] = Vsrc[(bs0 + r) * VV + c];
    }
    __syncthreads();
    if (tid < 8) {
        float s = 0.f, ss = 0.f;
        for (int c = 0; c < VV; c++) {
            float x = xt[c * 8 + tid];
            s += x; ss += x * x;
        }
        g_sv[bs0 + tid] = s;
        g_sq[bs0 + tid] = ss;
    }

    float acc[6];
    #pragma unroll
    for (int i = 0; i < 6; i++) acc[i] = 0.f;

    for (int h = 0; h < 2; h++) {
        __syncthreads();
        const float4* src = (const float4*)(g_Wall + h * 64 * 192);
        float4* dst = (float4*)ws;
        for (int idx = tid; idx < 3072; idx += 256) dst[idx] = src[idx];
        __syncthreads();
        #pragma unroll 4
        for (int c = 0; c < 64; c++) {
            float x = xt[(h * 64 + c) * 8 + ty];
            const float* wr = ws + c * 192 + tx;
            #pragma unroll
            for (int i = 0; i < 6; i++) acc[i] = fmaf(x, wr[i * 32], acc[i]);
        }
    }
    // transposed store: G1T[n][bs]
    #pragma unroll
    for (int i = 0; i < 6; i++)
        g_G1T[(size_t)(tx + 32 * i) * (BB * SS) + bs0 + ty] = acc[i];
}

// ---------------- per-(b,d): LN(V_dst) -> q, and wd GEMV (4 bd per block) ----------------
__global__ void __launch_bounds__(512) qwd_kernel(
    const float* __restrict__ Vdst, const float* __restrict__ g_vd,
    const float* __restrict__ b_vd, const float* __restrict__ Wq,
    const float* __restrict__ bq, const float* __restrict__ We) {
    __shared__ float vrow[4][VV];
    __shared__ float vn[4][VV];
    __shared__ float rsum[4][4], rsq[4][4];
    __shared__ float smu[4], srstd[4];

    int grp = threadIdx.x >> 7;      // 0..3
    int tid = threadIdx.x & 127;     // 0..127
    int bd = blockIdx.x * 4 + grp;

    float x = Vdst[bd * VV + tid];
    vrow[grp][tid] = x;

    float s = x, ss = x * x;
    for (int o = 16; o; o >>= 1) {
        s  += __shfl_down_sync(0xffffffffu, s, o);
        ss += __shfl_down_sync(0xffffffffu, ss, o);
    }
    if ((tid & 31) == 0) { rsum[grp][tid >> 5] = s; rsq[grp][tid >> 5] = ss; }
    __syncthreads();
    if (tid == 0) {
        float S = rsum[grp][0] + rsum[grp][1] + rsum[grp][2] + rsum[grp][3];
        float Q = rsq[grp][0] + rsq[grp][1] + rsq[grp][2] + rsq[grp][3];
        float m = S * (1.f / VV);
        float var = Q * (1.f / VV) - m * m;
        smu[grp] = m;
        srstd[grp] = rsqrtf(var + LN_EPS);
    }
    __syncthreads();
    vn[grp][tid] = (x - smu[grp]) * srstd[grp] * g_vd[tid] + b_vd[tid];
    __syncthreads();

    if (tid < 64) {
        float q = bq[tid];
        #pragma unroll 4
        for (int j = 0; j < VV; j++) q += vn[grp][j] * __ldg(Wq + j * 64 + tid);
        g_q[bd * 64 + tid] = fmaxf(q, 0.f);
    } else {
        int t = tid - 64;
        float w = 0.f;
        #pragma unroll 4
        for (int j = 0; j < VV; j++) w += vrow[grp][j] * __ldg(We + (128 + j) * 64 + t);
        g_wd[bd * 64 + t] = w;
    }
}

// ---------------- A_new == 1.0 exactly ----------------
__global__ void fill_a(float* __restrict__ outA) {
    int idx = blockIdx.x * 1024 + threadIdx.x;
    outA[idx] = 1.0f;
}

// ---------------- main fused kernel: one (b, d) per block, 256 s-rows, 2 CTAs/SM ----------------
__global__ void __launch_bounds__(256, 2) main_kernel(
    const float* __restrict__ Egl, const float* __restrict__ A,
    const float* __restrict__ be, float* __restrict__ outE) {
    extern __shared__ __align__(16) unsigned char smm[];
    int tid = threadIdx.x;
    int lane = tid & 31, wid = tid >> 5;     // 8 warps
    int bx = blockIdx.x;
    int d = bx & 255, b = bx >> 8;
    int bd = b * DD + d;

    float* qs   = (float*)(smm + OFF_QS);
    float* wds  = (float*)(smm + OFF_WDS);
    float* s1k  = (float*)(smm + OFF_S1K);
    float* s2k  = (float*)(smm + OFF_S2K);
    float* s1v  = (float*)(smm + OFF_S1V);
    float* s2v  = (float*)(smm + OFF_S2V);
    float* bes  = (float*)(smm + OFF_BES);
    float* ssum = (float*)(smm + OFF_SSUM);
    float* ssq  = (float*)(smm + OFF_SSQ);
    float* red  = (float*)(smm + OFF_RED);
    float* db   = (float*)(smm + DBX_OFF);
    if (tid < 64) {
        qs[tid]  = g_q[bd * 64 + tid];
        wds[tid] = g_wd[bd * 64 + tid];
        s1k[tid] = g_S1k[tid]; s2k[tid] = g_S2k[tid];
        s1v[tid] = g_S1v[tid]; s2v[tid] = g_S2v[tid];
        bes[tid] = be[tid];
    }

    // stage W2^T hi/lo into smem
    {
        const uint4* sh = (const uint4*)g_WTh;
        const uint4* sl = (const uint4*)g_WTl;
        uint4* dh = (uint4*)(smm + WH_OFF);
        uint4* dl = (uint4*)(smm + WL_OFF);
        #pragma unroll 4
        for (int i = tid; i < 1728; i += 256) { dh[i] = sh[i]; dl[i] = sl[i]; }
    }

    // ---- chunked X staging (coalesced) + per-chunk fragment pickup ----
    int g = lane >> 2, tc = lane & 3;
    uint32_t ahf[2][4][4], alf[2][4][4];
    int mychunk = wid >> 1;
    #pragma unroll 1
    for (int c = 0; c < 4; c++) {
        #pragma unroll
        for (int it = 0; it < 4; it++) {
            int idx = it * 256 + tid;        // 0..1023
            int lrow = idx >> 4;             // 0..63
            int seg = idx & 15;              // 0..15
            int row = c * 64 + lrow;
            float4 u = __ldg((const float4*)(Egl + ((size_t)(b * SS + row) * DD + d) * EE) + seg);
            float ps = u.x + u.y + u.z + u.w;
            float pq = u.x * u.x + u.y * u.y + u.z * u.z + u.w * u.w;
            #pragma unroll
            for (int o = 8; o; o >>= 1) {
                ps += __shfl_xor_sync(0xffffffffu, ps, o);
                pq += __shfl_xor_sync(0xffffffffu, pq, o);
            }
            if ((lane & 15) == 0) { ssum[row] = ps; ssq[row] = pq; }
            float x[4] = {u.x, u.y, u.z, u.w};
            uint32_t hp[2], lp[2];
            #pragma unroll
            for (int t = 0; t < 2; t++) {
                float a0 = x[2 * t], a1 = x[2 * t + 1];
                __nv_bfloat16 h0 = __float2bfloat16(a0), h1 = __float2bfloat16(a1);
                __nv_bfloat16 l0 = __float2bfloat16(a0 - __bfloat162float(h0));
                __nv_bfloat16 l1 = __float2bfloat16(a1 - __bfloat162float(h1));
                __nv_bfloat162 ph; ph.x = h0; ph.y = h1;
                __nv_bfloat162 pl; pl.x = l0; pl.y = l1;
                hp[t] = *(uint32_t*)&ph; lp[t] = *(uint32_t*)&pl;
            }
            uint32_t boff = (uint32_t)(lrow * 72 + seg * 4) * 2;
            *(uint2*)(smm + XH_OFF + boff) = make_uint2(hp[0], hp[1]);
            *(uint2*)(smm + XL_OFF + boff) = make_uint2(lp[0], lp[1]);
        }
        __syncthreads();
        if (mychunk == c) {
            int rb = (wid & 1) * 32 + g;
            #pragma unroll
            for (int mt = 0; mt < 2; mt++) {
                int r0 = rb + mt * 16;
                #pragma unroll
                for (int ks = 0; ks < 4; ks++) {
                    int c0 = tc * 2 + 16 * ks;
                    ahf[mt][ks][0] = *(const uint32_t*)(smm + XH_OFF + (r0 * 72 + c0) * 2);
                    ahf[mt][ks][1] = *(const uint32_t*)(smm + XH_OFF + ((r0 + 8) * 72 + c0) * 2);
                    ahf[mt][ks][2] = *(const uint32_t*)(smm + XH_OFF + (r0 * 72 + c0 + 8) * 2);
                    ahf[mt][ks][3] = *(const uint32_t*)(smm + XH_OFF + ((r0 + 8) * 72 + c0 + 8) * 2);
                    alf[mt][ks][0] = *(const uint32_t*)(smm + XL_OFF + (r0 * 72 + c0) * 2);
                    alf[mt][ks][1] = *(const uint32_t*)(smm + XL_OFF + ((r0 + 8) * 72 + c0) * 2);
                    alf[mt][ks][2] = *(const uint32_t*)(smm + XL_OFF + (r0 * 72 + c0 + 8) * 2);
                    alf[mt][ks][3] = *(const uint32_t*)(smm + XL_OFF + ((r0 + 8) * 72 + c0 + 8) * 2);
                }
            }
        }
        __syncthreads();
    }

    // per-thread row r = tid: LN stats
    int r = tid;
    size_t bs = (size_t)(b * SS + r);
    int gbs = b * SS + r;
    float av = __ldg(A + bs * DD + d);
    float mu = (av * g_sv[bs] + ssum[r]) * (1.f / CC);
    float msq = (av * av * g_sq[bs] + ssq[r]) * (1.f / CC);
    float rstd = rsqrtf(msq - mu * mu + LN_EPS);

    float sc[8];
    #pragma unroll
    for (int h = 0; h < 8; h++) sc[h] = 0.f;

    // ---- 6 phases of 32 columns each ----
    #pragma unroll 1
    for (int p = 0; p < 6; p++) {
        // GEMM: cols p*32 .. p*32+31 into db[256][33]
        #pragma unroll 1
        for (int nt = 0; nt < 4; nt++) {
            int n = p * 32 + nt * 8 + g;
            uint32_t bhf[4][2], blf[4][2];
            #pragma unroll
            for (int ks = 0; ks < 4; ks++) {
                int kk = tc * 2 + 16 * ks;
                bhf[ks][0] = *(const uint32_t*)(smm + WH_OFF + (n * 72 + kk) * 2);
                bhf[ks][1] = *(const uint32_t*)(smm + WH_OFF + (n * 72 + kk + 8) * 2);
                blf[ks][0] = *(const uint32_t*)(smm + WL_OFF + (n * 72 + kk) * 2);
                blf[ks][1] = *(const uint32_t*)(smm + WL_OFF + (n * 72 + kk + 8) * 2);
            }
            float acc[2][4];
            #pragma unroll
            for (int mt = 0; mt < 2; mt++)
                #pragma unroll
                for (int i = 0; i < 4; i++) acc[mt][i] = 0.f;
            #pragma unroll
            for (int ks = 0; ks < 4; ks++) {
                #pragma unroll
                for (int mt = 0; mt < 2; mt++) {
                    mma16816(acc[mt], ahf[mt][ks], bhf[ks]);
                    mma16816(acc[mt], alf[mt][ks], bhf[ks]);
                    mma16816(acc[mt], ahf[mt][ks], blf[ks]);
                }
            }
            #pragma unroll
            for (int mt = 0; mt < 2; mt++) {
                int r0 = wid * 32 + mt * 16 + g;
                int col = nt * 8 + tc * 2;
                db[r0 * 33 + col]           = acc[mt][0];
                db[r0 * 33 + col + 1]       = acc[mt][1];
                db[(r0 + 8) * 33 + col]     = acc[mt][2];
                db[(r0 + 8) * 33 + col + 1] = acc[mt][3];
            }
        }
        __syncthreads();

        // epilogue (all G1 reads via transposed G1T: coalesced across threads)
        if (p < 2) {
            #pragma unroll
            for (int j = 0; j < 32; j++) {
                int jg = p * 32 + j;
                float gv = __ldg(g_G1T + (size_t)jg * (BB * SS) + gbs);
                float yf = av * gv + db[r * 33 + j];
                float kk = fmaxf(rstd * (yf - mu * s1k[jg]) + s2k[jg], 0.f);
                sc[jg >> 3] += qs[jg] * kk;
            }
            if (p == 1) {
                float mx = sc[0] * 0.35355339059327373f;
                #pragma unroll
                for (int h = 0; h < 8; h++) { sc[h] *= 0.35355339059327373f; mx = fmaxf(mx, sc[h]); }
                float sum = 0.f;
                #pragma unroll
                for (int h = 0; h < 8; h++) { sc[h] = __expf(sc[h] - mx); sum += sc[h]; }
                float inv = 1.f / sum;
                #pragma unroll
                for (int h = 0; h < 8; h++) sc[h] *= inv;
            }
            __syncthreads();
        } else if (p < 4) {
            int q = p - 2;
            #pragma unroll
            for (int j = 0; j < 32; j++) {
                int jg = q * 32 + j;
                float gv = __ldg(g_G1T + (size_t)(64 + jg) * (BB * SS) + gbs);
                float yf = av * gv + db[r * 33 + j];
                float vv = fmaxf(rstd * (yf - mu * s1v[jg]) + s2v[jg], 0.f);
                db[r * 33 + j] = sc[jg >> 3] * vv;
            }
            __syncthreads();
            // deterministic column reduce: 8 partials of 32 rows
            {
                int col = tid & 31, qq = tid >> 5;
                float s = 0.f;
                int rr0 = qq * 32;
                #pragma unroll 8
                for (int rr = rr0; rr < rr0 + 32; rr++) s += db[rr * 33 + col];
                red[qq * 32 + col] = s;
            }
            __syncthreads();
            if (tid < 32) {
                float s = ((red[tid] + red[32 + tid]) + (red[64 + tid] + red[96 + tid]))
                        + ((red[128 + tid] + red[160 + tid]) + (red[192 + tid] + red[224 + tid]));
                g_o[(size_t)bd * 64 + q * 32 + tid] = s;
            }
            __syncthreads();
        } else {
            int q = p - 4;
            // compute relu(y) in place in db (per-thread row), then coalesced store pass
            #pragma unroll
            for (int j = 0; j < 32; j++) {
                int jg = q * 32 + j;
                float gv = __ldg(g_G1T + (size_t)(128 + jg) * (BB * SS) + gbs);
                float y = av * gv + db[r * 33 + j] + av * wds[jg] + bes[jg];
                db[r * 33 + j] = fmaxf(y, 0.f);
            }
            __syncthreads();
            // warp w stores rows w*32..w*32+31, coalesced across lanes (lane = col)
            #pragma unroll 4
            for (int rr = 0; rr < 32; rr++) {
                int row = wid * 32 + rr;
                outE[((size_t)(b * SS + row) * DD + d) * EE + q * 32 + lane] = db[row * 33 + lane];
            }
            if (p == 4) __syncthreads();
        }
    }
}

// ---------------- finalize: V_dst_out = V_dst + relu(o @ Wo + bo) ----------------
__global__ void __launch_bounds__(128) fin_kernel(
    const float* __restrict__ Vdst, const float* __restrict__ Wo,
    const float* __restrict__ bo, float* __restrict__ outV) {
    __shared__ float os[64];
    int bd = blockIdx.x;
    int tid = threadIdx.x;
    if (tid < 64) os[tid] = g_o[(size_t)bd * 64 + tid];
    __syncthreads();
    float a = bo[tid];
    #pragma unroll 4
    for (int t = 0; t < 64; t++) a += os[t] * __ldg(Wo + t * VV + tid);
    outV[bd * VV + tid] = Vdst[bd * VV + tid] + fmaxf(a, 0.f);
}

// ---------------- launch ----------------
extern "C" void kernel_launch(void* const* d_in, const int* in_sizes, int n_in,
                              void* d_out, int out_size) {
    const float* V_src = (const float*)d_in[0];
    const float* V_dst = (const float*)d_in[1];
    const float* E     = (const float*)d_in[2];
    const float* A     = (const float*)d_in[3];
    const float* g_vd  = (const float*)d_in[4];
    const float* b_vd  = (const float*)d_in[5];
    const float* g_in  = (const float*)d_in[6];
    const float* b_in  = (const float*)d_in[7];
    const float* Wq    = (const float*)d_in[8];
    const float* bq    = (const float*)d_in[9];
    const float* Wk    = (const float*)d_in[10];
    const float* bk    = (const float*)d_in[11];
    const float* Wv    = (const float*)d_in[12];
    const float* bv    = (const float*)d_in[13];
    const float* Wo    = (const float*)d_in[14];
    const float* bo    = (const float*)d_in[15];
    const float* We    = (const float*)d_in[16];
    const float* be    = (const float*)d_in[17];
    // d_in[18] = Wa, d_in[19] = ba: unused — softmax over singleton axis is exactly 1.

    float* outV = (float*)d_out;                       // [4,256,128]
    float* outE = outV + BB * DD * VV;                 // [4,256,256,64]
    float* outA = outE + (size_t)BB * SS * DD * EE;    // [4,256,256]

    const int SMEM_G1 = (1024 + 64 * 192) * (int)sizeof(float);
    cudaFuncSetAttribute(main_kernel, cudaFuncAttributeMaxDynamicSharedMemorySize, SMEM_MAIN);
    cudaFuncSetAttribute(g1_kernel, cudaFuncAttributeMaxDynamicSharedMemorySize, SMEM_G1);

    prep_wall<<<192, 192>>>(g_in, Wk, Wv, We);
    prep_sums<<<1, 128>>>(g_in, b_in, Wk, bk, Wv, bv);
    prep_wt<<<192, 64>>>();
    g1_kernel<<<BB * SS / 8, 256, SMEM_G1>>>(V_src);
    qwd_kernel<<<BB * DD / 4, 512>>>(V_dst, g_vd, b_vd, Wq, bq, We);
    fill_a<<<(BB * SS * DD) / 1024, 1024>>>(outA);
    main_kernel<<<BB * DD, 256, SMEM_MAIN>>>(E, A, be, outE);
    fin_kernel<<<BB * DD, 128>>>(V_dst, Wo, bo, outV);
}

// round 10
// speedup vs baseline: 1.6630x; 1.0237x over previous
#include <cuda_runtime.h>
#include <cuda_bf16.h>
#include <math.h>
#include <stdint.h>

// Problem constants
#define BB 4
#define SS 256
#define DD 256
#define VV 128
#define EE 64
#define CC 192
#define LN_EPS 1e-3f

// main-kernel smem byte offsets
#define WH_OFF  0
#define WL_OFF  27648
#define DBX_OFF 55296
#define XH_OFF  DBX_OFF
#define XL_OFF  (DBX_OFF + 9216)
#define AUX     89088
#define OFF_QS   (AUX)
#define OFF_WDS  (AUX + 256)
#define OFF_S1K  (AUX + 512)
#define OFF_S2K  (AUX + 768)
#define OFF_S1V  (AUX + 1024)
#define OFF_S2V  (AUX + 1280)
#define OFF_BES  (AUX + 1536)
#define OFF_SSUM (AUX + 1792)
#define OFF_SSQ  (AUX + 2816)
#define OFF_RED  (AUX + 3840)
#define SMEM_MAIN (AUX + 4864)   // 93952 bytes -> 2 CTAs/SM

// ---------------- device scratch ----------------
__device__ __align__(16) float g_Wall[128 * 192];    // only rows 0..127 needed (g1)
__device__ float g_S1k[64], g_S2k[64], g_S1v[64], g_S2v[64];
__device__ float g_q[BB * DD * 64];
__device__ float g_wd[BB * DD * 64];
__device__ float g_o[BB * DD * 64];
__device__ __align__(16) float g_G1T[192 * BB * SS];  // TRANSPOSED: [n][b*s]
__device__ float g_sv[BB * SS], g_sq[BB * SS];
__device__ __align__(16) __nv_bfloat16 g_WTh[192 * 72];  // W2^T hi, [n][k] padded
__device__ __align__(16) __nv_bfloat16 g_WTl[192 * 72];  // W2^T lo

// ---------------- mma.sync helper (baseline sm_80+ PTX) ----------------
__device__ __forceinline__ void mma16816(float* c, const uint32_t* a, const uint32_t* b) {
    asm volatile(
        "mma.sync.aligned.m16n8k16.row.col.f32.bf16.bf16.f32 "
        "{%0,%1,%2,%3}, {%4,%5,%6,%7}, {%8,%9}, {%0,%1,%2,%3};"
        : "+f"(c[0]), "+f"(c[1]), "+f"(c[2]), "+f"(c[3])
        : "r"(a[0]), "r"(a[1]), "r"(a[2]), "r"(a[3]), "r"(b[0]), "r"(b[1]));
}

// ---------------- prep: all weight preprocessing in one kernel ----------------
// blocks 0..127   : g_Wall rows 0..127 (for g1)
// blocks 128..319 : W2^T hi/lo bf16 images (row n = bid-128)
// block 320       : S1/S2 sums
__global__ void prep_all(const float* __restrict__ g_in, const float* __restrict__ b_in,
                         const float* __restrict__ Wk, const float* __restrict__ bk,
                         const float* __restrict__ Wv, const float* __restrict__ bv,
                         const float* __restrict__ We) {
    int bid = blockIdx.x;
    int tid = threadIdx.x;   // 192
    if (bid < 128) {
        int c = bid, j = tid;
        float g = g_in[c];
        float val;
        if (j < 64)        val = g * Wk[c * 64 + j];
        else if (j < 128)  val = g * Wv[c * 64 + (j - 64)];
        else               val = We[c * 64 + (j - 128)];       // c < 128
        g_Wall[c * 192 + j] = val;
    } else if (bid < 320) {
        int n = bid - 128;
        if (tid < 64) {
            int k = tid;
            int c = 128 + k;
            float g = g_in[c];
            float w;
            if (n < 64)        w = g * Wk[c * 64 + n];
            else if (n < 128)  w = g * Wv[c * 64 + (n - 64)];
            else               w = We[(c + 128) * 64 + (n - 128)];
            __nv_bfloat16 wh = __float2bfloat16(w);
            __nv_bfloat16 wl = __float2bfloat16(w - __bfloat162float(wh));
            g_WTh[n * 72 + k] = wh;
            g_WTl[n * 72 + k] = wl;
            if (k >= 56) {
                g_WTh[n * 72 + 8 + k] = __float2bfloat16(0.f);
                g_WTl[n * 72 + 8 + k] = __float2bfloat16(0.f);
            }
        }
    } else {
        if (tid < 64) {
            int j = tid;
            float s1 = 0.f, s2 = 0.f;
            for (int c = 0; c < CC; c++) {
                float w = Wk[c * 64 + j];
                s1 += g_in[c] * w;
                s2 += b_in[c] * w;
            }
            g_S1k[j] = s1;
            g_S2k[j] = s2 + bk[j];
        } else if (tid < 128) {
            int j = tid - 64;
            float s1 = 0.f, s2 = 0.f;
            for (int c = 0; c < CC; c++) {
                float w = Wv[c * 64 + j];
                s1 += g_in[c] * w;
                s2 += b_in[c] * w;
            }
            g_S1v[j] = s1;
            g_S2v[j] = s2 + bv[j];
        }
    }
}

// ---------------- G1T[n][bs] = (Vsrc @ Wall[0:128,:])^T  (+ row sums for LN) ----------------
__global__ void __launch_bounds__(256) g1_kernel(const float* __restrict__ Vsrc) {
    extern __shared__ float smf[];
    float* xt = smf;           // [128 c][8 r]
    float* ws = smf + 1024;    // [64 c][192 n]
    int bs0 = blockIdx.x * 8;
    int tid = threadIdx.x;
    int tx = tid & 31, ty = tid >> 5;

    for (int idx = tid; idx < 1024; idx += 256) {
        int c = idx & 127, r = idx >> 7;
        xt[c * 8 + r] = Vsrc[(bs0 + r) * VV + c];
    }
    __syncthreads();
    if (tid < 8) {
        float s = 0.f, ss = 0.f;
        for (int c = 0; c < VV; c++) {
            float x = xt[c * 8 + tid];
            s += x; ss += x * x;
        }
        g_sv[bs0 + tid] = s;
        g_sq[bs0 + tid] = ss;
    }

    float acc[6];
    #pragma unroll
    for (int i = 0; i < 6; i++) acc[i] = 0.f;

    for (int h = 0; h < 2; h++) {
        __syncthreads();
        const float4* src = (const float4*)(g_Wall + h * 64 * 192);
        float4* dst = (float4*)ws;
        for (int idx = tid; idx < 3072; idx += 256) dst[idx] = src[idx];
        __syncthreads();
        #pragma unroll 4
        for (int c = 0; c < 64; c++) {
            float x = xt[(h * 64 + c) * 8 + ty];
            const float* wr = ws + c * 192 + tx;
            #pragma unroll
            for (int i = 0; i < 6; i++) acc[i] = fmaf(x, wr[i * 32], acc[i]);
        }
    }
    #pragma unroll
    for (int i = 0; i < 6; i++)
        g_G1T[(size_t)(tx + 32 * i) * (BB * SS) + bs0 + ty] = acc[i];
}

// ---------------- per-(b,d): LN(V_dst) -> q, and wd GEMV (4 bd per block) ----------------
__global__ void __launch_bounds__(512) qwd_kernel(
    const float* __restrict__ Vdst, const float* __restrict__ g_vd,
    const float* __restrict__ b_vd, const float* __restrict__ Wq,
    const float* __restrict__ bq, const float* __restrict__ We) {
    __shared__ float vrow[4][VV];
    __shared__ float vn[4][VV];
    __shared__ float rsum[4][4], rsq[4][4];
    __shared__ float smu[4], srstd[4];

    int grp = threadIdx.x >> 7;
    int tid = threadIdx.x & 127;
    int bd = blockIdx.x * 4 + grp;

    float x = Vdst[bd * VV + tid];
    vrow[grp][tid] = x;

    float s = x, ss = x * x;
    for (int o = 16; o; o >>= 1) {
        s  += __shfl_down_sync(0xffffffffu, s, o);
        ss += __shfl_down_sync(0xffffffffu, ss, o);
    }
    if ((tid & 31) == 0) { rsum[grp][tid >> 5] = s; rsq[grp][tid >> 5] = ss; }
    __syncthreads();
    if (tid == 0) {
        float S = rsum[grp][0] + rsum[grp][1] + rsum[grp][2] + rsum[grp][3];
        float Q = rsq[grp][0] + rsq[grp][1] + rsq[grp][2] + rsq[grp][3];
        float m = S * (1.f / VV);
        float var = Q * (1.f / VV) - m * m;
        smu[grp] = m;
        srstd[grp] = rsqrtf(var + LN_EPS);
    }
    __syncthreads();
    vn[grp][tid] = (x - smu[grp]) * srstd[grp] * g_vd[tid] + b_vd[tid];
    __syncthreads();

    if (tid < 64) {
        float q = bq[tid];
        #pragma unroll 4
        for (int j = 0; j < VV; j++) q += vn[grp][j] * __ldg(Wq + j * 64 + tid);
        g_q[bd * 64 + tid] = fmaxf(q, 0.f);
    } else {
        int t = tid - 64;
        float w = 0.f;
        #pragma unroll 4
        for (int j = 0; j < VV; j++) w += vrow[grp][j] * __ldg(We + (128 + j) * 64 + t);
        g_wd[bd * 64 + t] = w;
    }
}

// ---------------- A_new == 1.0 exactly ----------------
__global__ void fill_a(float* __restrict__ outA) {
    int idx = blockIdx.x * 1024 + threadIdx.x;
    outA[idx] = 1.0f;
}

// ---------------- main fused kernel: one (b, d) per block, 256 s-rows, 2 CTAs/SM ----------------
__global__ void __launch_bounds__(256, 2) main_kernel(
    const float* __restrict__ Egl, const float* __restrict__ A,
    const float* __restrict__ be, float* __restrict__ outE) {
    extern __shared__ __align__(16) unsigned char smm[];
    int tid = threadIdx.x;
    int lane = tid & 31, wid = tid >> 5;
    int bx = blockIdx.x;
    int d = bx & 255, b = bx >> 8;
    int bd = b * DD + d;

    float* qs   = (float*)(smm + OFF_QS);
    float* wds  = (float*)(smm + OFF_WDS);
    float* s1k  = (float*)(smm + OFF_S1K);
    float* s2k  = (float*)(smm + OFF_S2K);
    float* s1v  = (float*)(smm + OFF_S1V);
    float* s2v  = (float*)(smm + OFF_S2V);
    float* bes  = (float*)(smm + OFF_BES);
    float* ssum = (float*)(smm + OFF_SSUM);
    float* ssq  = (float*)(smm + OFF_SSQ);
    float* red  = (float*)(smm + OFF_RED);
    float* db   = (float*)(smm + DBX_OFF);
    if (tid < 64) {
        qs[tid]  = g_q[bd * 64 + tid];
        wds[tid] = g_wd[bd * 64 + tid];
        s1k[tid] = g_S1k[tid]; s2k[tid] = g_S2k[tid];
        s1v[tid] = g_S1v[tid]; s2v[tid] = g_S2v[tid];
        bes[tid] = be[tid];
    }

    // stage W2^T hi/lo into smem
    {
        const uint4* sh = (const uint4*)g_WTh;
        const uint4* sl = (const uint4*)g_WTl;
        uint4* dh = (uint4*)(smm + WH_OFF);
        uint4* dl = (uint4*)(smm + WL_OFF);
        #pragma unroll 4
        for (int i = tid; i < 1728; i += 256) { dh[i] = sh[i]; dl[i] = sl[i]; }
    }

    // ---- chunked X staging (coalesced) + per-chunk fragment pickup ----
    int g = lane >> 2, tc = lane & 3;
    uint32_t ahf[2][4][4], alf[2][4][4];
    int mychunk = wid >> 1;
    #pragma unroll 1
    for (int c = 0; c < 4; c++) {
        #pragma unroll
        for (int it = 0; it < 4; it++) {
            int idx = it * 256 + tid;
            int lrow = idx >> 4;
            int seg = idx & 15;
            int row = c * 64 + lrow;
            float4 u = __ldg((const float4*)(Egl + ((size_t)(b * SS + row) * DD + d) * EE) + seg);
            float ps = u.x + u.y + u.z + u.w;
            float pq = u.x * u.x + u.y * u.y + u.z * u.z + u.w * u.w;
            #pragma unroll
            for (int o = 8; o; o >>= 1) {
                ps += __shfl_xor_sync(0xffffffffu, ps, o);
                pq += __shfl_xor_sync(0xffffffffu, pq, o);
            }
            if ((lane & 15) == 0) { ssum[row] = ps; ssq[row] = pq; }
            float x[4] = {u.x, u.y, u.z, u.w};
            uint32_t hp[2], lp[2];
            #pragma unroll
            for (int t = 0; t < 2; t++) {
                float a0 = x[2 * t], a1 = x[2 * t + 1];
                __nv_bfloat16 h0 = __float2bfloat16(a0), h1 = __float2bfloat16(a1);
                __nv_bfloat16 l0 = __float2bfloat16(a0 - __bfloat162float(h0));
                __nv_bfloat16 l1 = __float2bfloat16(a1 - __bfloat162float(h1));
                __nv_bfloat162 ph; ph.x = h0; ph.y = h1;
                __nv_bfloat162 pl; pl.x = l0; pl.y = l1;
                hp[t] = *(uint32_t*)&ph; lp[t] = *(uint32_t*)&pl;
            }
            uint32_t boff = (uint32_t)(lrow * 72 + seg * 4) * 2;
            *(uint2*)(smm + XH_OFF + boff) = make_uint2(hp[0], hp[1]);
            *(uint2*)(smm + XL_OFF + boff) = make_uint2(lp[0], lp[1]);
        }
        __syncthreads();
        if (mychunk == c) {
            int rb = (wid & 1) * 32 + g;
            #pragma unroll
            for (int mt = 0; mt < 2; mt++) {
                int r0 = rb + mt * 16;
                #pragma unroll
                for (int ks = 0; ks < 4; ks++) {
                    int c0 = tc * 2 + 16 * ks;
                    ahf[mt][ks][0] = *(const uint32_t*)(smm + XH_OFF + (r0 * 72 + c0) * 2);
                    ahf[mt][ks][1] = *(const uint32_t*)(smm + XH_OFF + ((r0 + 8) * 72 + c0) * 2);
                    ahf[mt][ks][2] = *(const uint32_t*)(smm + XH_OFF + (r0 * 72 + c0 + 8) * 2);
                    ahf[mt][ks][3] = *(const uint32_t*)(smm + XH_OFF + ((r0 + 8) * 72 + c0 + 8) * 2);
                    alf[mt][ks][0] = *(const uint32_t*)(smm + XL_OFF + (r0 * 72 + c0) * 2);
                    alf[mt][ks][1] = *(const uint32_t*)(smm + XL_OFF + ((r0 + 8) * 72 + c0) * 2);
                    alf[mt][ks][2] = *(const uint32_t*)(smm + XL_OFF + (r0 * 72 + c0 + 8) * 2);
                    alf[mt][ks][3] = *(const uint32_t*)(smm + XL_OFF + ((r0 + 8) * 72 + c0 + 8) * 2);
                }
            }
        }
        __syncthreads();
    }

    // per-thread row r = tid: LN stats
    int r = tid;
    size_t bs = (size_t)(b * SS + r);
    int gbs = b * SS + r;
    float av = __ldg(A + bs * DD + d);
    float mu = (av * g_sv[bs] + ssum[r]) * (1.f / CC);
    float msq = (av * av * g_sq[bs] + ssq[r]) * (1.f / CC);
    float rstd = rsqrtf(msq - mu * mu + LN_EPS);

    float sc[8];
    #pragma unroll
    for (int h = 0; h < 8; h++) sc[h] = 0.f;

    // ---- 6 phases of 32 columns each ----
    #pragma unroll 1
    for (int p = 0; p < 6; p++) {
        // GEMM: cols p*32 .. p*32+31 into db[256][33]
        #pragma unroll 1
        for (int nt = 0; nt < 4; nt++) {
            int n = p * 32 + nt * 8 + g;
            uint32_t bhf[4][2], blf[4][2];
            #pragma unroll
            for (int ks = 0; ks < 4; ks++) {
                int kk = tc * 2 + 16 * ks;
                bhf[ks][0] = *(const uint32_t*)(smm + WH_OFF + (n * 72 + kk) * 2);
                bhf[ks][1] = *(const uint32_t*)(smm + WH_OFF + (n * 72 + kk + 8) * 2);
                blf[ks][0] = *(const uint32_t*)(smm + WL_OFF + (n * 72 + kk) * 2);
                blf[ks][1] = *(const uint32_t*)(smm + WL_OFF + (n * 72 + kk + 8) * 2);
            }
            // 6 independent accumulator chains (depth 4) instead of 2 chains of depth 12
            float a0[2][4], a1[2][4], a2[2][4];
            #pragma unroll
            for (int mt = 0; mt < 2; mt++)
                #pragma unroll
                for (int i = 0; i < 4; i++) { a0[mt][i] = 0.f; a1[mt][i] = 0.f; a2[mt][i] = 0.f; }
            #pragma unroll
            for (int ks = 0; ks < 4; ks++) {
                #pragma unroll
                for (int mt = 0; mt < 2; mt++) {
                    mma16816(a0[mt], ahf[mt][ks], bhf[ks]);
                    mma16816(a1[mt], alf[mt][ks], bhf[ks]);
                    mma16816(a2[mt], ahf[mt][ks], blf[ks]);
                }
            }
            #pragma unroll
            for (int mt = 0; mt < 2; mt++) {
                int r0 = wid * 32 + mt * 16 + g;
                int col = nt * 8 + tc * 2;
                db[r0 * 33 + col]           = a0[mt][0] + a1[mt][0] + a2[mt][0];
                db[r0 * 33 + col + 1]       = a0[mt][1] + a1[mt][1] + a2[mt][1];
                db[(r0 + 8) * 33 + col]     = a0[mt][2] + a1[mt][2] + a2[mt][2];
                db[(r0 + 8) * 33 + col + 1] = a0[mt][3] + a1[mt][3] + a2[mt][3];
            }
        }
        __syncthreads();

        // epilogue (coalesced G1T reads)
        if (p < 2) {
            #pragma unroll
            for (int j = 0; j < 32; j++) {
                int jg = p * 32 + j;
                float gv = __ldg(g_G1T + (size_t)jg * (BB * SS) + gbs);
                float yf = av * gv + db[r * 33 + j];
                float kk = fmaxf(rstd * (yf - mu * s1k[jg]) + s2k[jg], 0.f);
                sc[jg >> 3] += qs[jg] * kk;
            }
            if (p == 1) {
                float mx = sc[0] * 0.35355339059327373f;
                #pragma unroll
                for (int h = 0; h < 8; h++) { sc[h] *= 0.35355339059327373f; mx = fmaxf(mx, sc[h]); }
                float sum = 0.f;
                #pragma unroll
                for (int h = 0; h < 8; h++) { sc[h] = __expf(sc[h] - mx); sum += sc[h]; }
                float inv = 1.f / sum;
                #pragma unroll
                for (int h = 0; h < 8; h++) sc[h] *= inv;
            }
            __syncthreads();
        } else if (p < 4) {
            int q = p - 2;
            #pragma unroll
            for (int j = 0; j < 32; j++) {
                int jg = q * 32 + j;
                float gv = __ldg(g_G1T + (size_t)(64 + jg) * (BB * SS) + gbs);
                float yf = av * gv + db[r * 33 + j];
                float vv = fmaxf(rstd * (yf - mu * s1v[jg]) + s2v[jg], 0.f);
                db[r * 33 + j] = sc[jg >> 3] * vv;
            }
            __syncthreads();
            {
                int col = tid & 31, qq = tid >> 5;
                float s = 0.f;
                int rr0 = qq * 32;
                #pragma unroll 8
                for (int rr = rr0; rr < rr0 + 32; rr++) s += db[rr * 33 + col];
                red[qq * 32 + col] = s;
            }
            __syncthreads();
            if (tid < 32) {
                float s = ((red[tid] + red[32 + tid]) + (red[64 + tid] + red[96 + tid]))
                        + ((red[128 + tid] + red[160 + tid]) + (red[192 + tid] + red[224 + tid]));
                g_o[(size_t)bd * 64 + q * 32 + tid] = s;
            }
            __syncthreads();
        } else {
            int q = p - 4;
            #pragma unroll
            for (int j = 0; j < 32; j++) {
                int jg = q * 32 + j;
                float gv = __ldg(g_G1T + (size_t)(128 + jg) * (BB * SS) + gbs);
                float y = av * gv + db[r * 33 + j] + av * wds[jg] + bes[jg];
                db[r * 33 + j] = fmaxf(y, 0.f);
            }
            __syncthreads();
            #pragma unroll 4
            for (int rr = 0; rr < 32; rr++) {
                int row = wid * 32 + rr;
                outE[((size_t)(b * SS + row) * DD + d) * EE + q * 32 + lane] = db[row * 33 + lane];
            }
            if (p == 4) __syncthreads();
        }
    }
}

// ---------------- finalize: V_dst_out = V_dst + relu(o @ Wo + bo) ----------------
__global__ void __launch_bounds__(128) fin_kernel(
    const float* __restrict__ Vdst, const float* __restrict__ Wo,
    const float* __restrict__ bo, float* __restrict__ outV) {
    __shared__ float os[64];
    int bd = blockIdx.x;
    int tid = threadIdx.x;
    if (tid < 64) os[tid] = g_o[(size_t)bd * 64 + tid];
    __syncthreads();
    float a = bo[tid];
    #pragma unroll 4
    for (int t = 0; t < 64; t++) a += os[t] * __ldg(Wo + t * VV + tid);
    outV[bd * VV + tid] = Vdst[bd * VV + tid] + fmaxf(a, 0.f);
}

// ---------------- launch ----------------
extern "C" void kernel_launch(void* const* d_in, const int* in_sizes, int n_in,
                              void* d_out, int out_size) {
    const float* V_src = (const float*)d_in[0];
    const float* V_dst = (const float*)d_in[1];
    const float* E     = (const float*)d_in[2];
    const float* A     = (const float*)d_in[3];
    const float* g_vd  = (const float*)d_in[4];
    const float* b_vd  = (const float*)d_in[5];
    const float* g_in  = (const float*)d_in[6];
    const float* b_in  = (const float*)d_in[7];
    const float* Wq    = (const float*)d_in[8];
    const float* bq    = (const float*)d_in[9];
    const float* Wk    = (const float*)d_in[10];
    const float* bk    = (const float*)d_in[11];
    const float* Wv    = (const float*)d_in[12];
    const float* bv    = (const float*)d_in[13];
    const float* Wo    = (const float*)d_in[14];
    const float* bo    = (const float*)d_in[15];
    const float* We    = (const float*)d_in[16];
    const float* be    = (const float*)d_in[17];
    // d_in[18] = Wa, d_in[19] = ba: unused — softmax over singleton axis is exactly 1.

    float* outV = (float*)d_out;                       // [4,256,128]
    float* outE = outV + BB * DD * VV;                 // [4,256,256,64]
    float* outA = outE + (size_t)BB * SS * DD * EE;    // [4,256,256]

    const int SMEM_G1 = (1024 + 64 * 192) * (int)sizeof(float);
    cudaFuncSetAttribute(main_kernel, cudaFuncAttributeMaxDynamicSharedMemorySize, SMEM_MAIN);
    cudaFuncSetAttribute(g1_kernel, cudaFuncAttributeMaxDynamicSharedMemorySize, SMEM_G1);

    prep_all<<<321, 192>>>(g_in, b_in, Wk, bk, Wv, bv, We);
    g1_kernel<<<BB * SS / 8, 256, SMEM_G1>>>(V_src);
    qwd_kernel<<<BB * DD / 4, 512>>>(V_dst, g_vd, b_vd, Wq, bq, We);
    fill_a<<<(BB * SS * DD) / 1024, 1024>>>(outA);
    main_kernel<<<BB * DD, 256, SMEM_MAIN>>>(E, A, be, outE);
    fin_kernel<<<BB * DD, 128>>>(V_dst, Wo, bo, outV);
}

// round 11
// speedup vs baseline: 1.7391x; 1.0458x over previous
#include <cuda_runtime.h>
#include <cuda_fp16.h>
#include <math.h>
#include <stdint.h>

// Problem constants
#define BB 4
#define SS 256
#define DD 256
#define VV 128
#define EE 64
#define CC 192
#define LN_EPS 1e-3f

// main-kernel smem byte offsets
// W hi: [192 n][72 k] fp16 (27648 B). X chunk hi/lo transient under db [256][33] f32.
#define WH_OFF  0
#define DBX_OFF 27648
#define XH_OFF  DBX_OFF
#define XL_OFF  (DBX_OFF + 9216)
#define AUX     61440
#define OFF_QS   (AUX)
#define OFF_WDS  (AUX + 256)
#define OFF_S1K  (AUX + 512)
#define OFF_S2K  (AUX + 768)
#define OFF_S1V  (AUX + 1024)
#define OFF_S2V  (AUX + 1280)
#define OFF_BES  (AUX + 1536)
#define OFF_SSUM (AUX + 1792)
#define OFF_SSQ  (AUX + 2816)
#define OFF_RED  (AUX + 3840)
#define SMEM_MAIN (AUX + 4864)   // 66304 bytes

// ---------------- device scratch ----------------
__device__ __align__(16) float g_Wall[128 * 192];    // rows 0..127 (for g1)
__device__ float g_S1k[64], g_S2k[64], g_S1v[64], g_S2v[64];
__device__ float g_q[BB * DD * 64];
__device__ float g_wd[BB * DD * 64];
__device__ float g_o[BB * DD * 64];
__device__ __align__(16) float g_G1T[192 * BB * SS];  // TRANSPOSED: [n][b*s]
__device__ float g_sv[BB * SS], g_sq[BB * SS];
__device__ __align__(16) __half g_WTh[192 * 72];      // W2^T fp16, [n][k] padded

// ---------------- mma.sync helper (fp16 in, fp32 accum; baseline sm_80+ PTX) ----------------
__device__ __forceinline__ void mma16816(float* c, const uint32_t* a, const uint32_t* b) {
    asm volatile(
        "mma.sync.aligned.m16n8k16.row.col.f32.f16.f16.f32 "
        "{%0,%1,%2,%3}, {%4,%5,%6,%7}, {%8,%9}, {%0,%1,%2,%3};"
        : "+f"(c[0]), "+f"(c[1]), "+f"(c[2]), "+f"(c[3])
        : "r"(a[0]), "r"(a[1]), "r"(a[2]), "r"(a[3]), "r"(b[0]), "r"(b[1]));
}

// ---------------- prep: all weight preprocessing in one kernel ----------------
__global__ void prep_all(const float* __restrict__ g_in, const float* __restrict__ b_in,
                         const float* __restrict__ Wk, const float* __restrict__ bk,
                         const float* __restrict__ Wv, const float* __restrict__ bv,
                         const float* __restrict__ We) {
    int bid = blockIdx.x;
    int tid = threadIdx.x;   // 192
    if (bid < 128) {
        int c = bid, j = tid;
        float g = g_in[c];
        float val;
        if (j < 64)        val = g * Wk[c * 64 + j];
        else if (j < 128)  val = g * Wv[c * 64 + (j - 64)];
        else               val = We[c * 64 + (j - 128)];       // c < 128
        g_Wall[c * 192 + j] = val;
    } else if (bid < 320) {
        int n = bid - 128;
        if (tid < 64) {
            int k = tid;
            int c = 128 + k;
            float g = g_in[c];
            float w;
            if (n < 64)        w = g * Wk[c * 64 + n];
            else if (n < 128)  w = g * Wv[c * 64 + (n - 64)];
            else               w = We[(c + 128) * 64 + (n - 128)];
            g_WTh[n * 72 + k] = __float2half_rn(w);
            if (k >= 56) g_WTh[n * 72 + 8 + k] = __float2half_rn(0.f);
        }
    } else {
        if (tid < 64) {
            int j = tid;
            float s1 = 0.f, s2 = 0.f;
            for (int c = 0; c < CC; c++) {
                float w = Wk[c * 64 + j];
                s1 += g_in[c] * w;
                s2 += b_in[c] * w;
            }
            g_S1k[j] = s1;
            g_S2k[j] = s2 + bk[j];
        } else if (tid < 128) {
            int j = tid - 64;
            float s1 = 0.f, s2 = 0.f;
            for (int c = 0; c < CC; c++) {
                float w = Wv[c * 64 + j];
                s1 += g_in[c] * w;
                s2 += b_in[c] * w;
            }
            g_S1v[j] = s1;
            g_S2v[j] = s2 + bv[j];
        }
    }
}

// ---------------- G1T[n][bs] = (Vsrc @ Wall[0:128,:])^T  (+ row sums for LN) ----------------
__global__ void __launch_bounds__(256) g1_kernel(const float* __restrict__ Vsrc) {
    extern __shared__ float smf[];
    float* xt = smf;           // [128 c][8 r]
    float* ws = smf + 1024;    // [64 c][192 n]
    int bs0 = blockIdx.x * 8;
    int tid = threadIdx.x;
    int tx = tid & 31, ty = tid >> 5;

    for (int idx = tid; idx < 1024; idx += 256) {
        int c = idx & 127, r = idx >> 7;
        xt[c * 8 + r] = Vsrc[(bs0 + r) * VV + c];
    }
    __syncthreads();
    if (tid < 8) {
        float s = 0.f, ss = 0.f;
        for (int c = 0; c < VV; c++) {
            float x = xt[c * 8 + tid];
            s += x; ss += x * x;
        }
        g_sv[bs0 + tid] = s;
        g_sq[bs0 + tid] = ss;
    }

    float acc[6];
    #pragma unroll
    for (int i = 0; i < 6; i++) acc[i] = 0.f;

    for (int h = 0; h < 2; h++) {
        __syncthreads();
        const float4* src = (const float4*)(g_Wall + h * 64 * 192);
        float4* dst = (float4*)ws;
        for (int idx = tid; idx < 3072; idx += 256) dst[idx] = src[idx];
        __syncthreads();
        #pragma unroll 4
        for (int c = 0; c < 64; c++) {
            float x = xt[(h * 64 + c) * 8 + ty];
            const float* wr = ws + c * 192 + tx;
            #pragma unroll
            for (int i = 0; i < 6; i++) acc[i] = fmaf(x, wr[i * 32], acc[i]);
        }
    }
    #pragma unroll
    for (int i = 0; i < 6; i++)
        g_G1T[(size_t)(tx + 32 * i) * (BB * SS) + bs0 + ty] = acc[i];
}

// ---------------- per-(b,d): LN(V_dst) -> q, and wd GEMV (4 bd per block) ----------------
__global__ void __launch_bounds__(512) qwd_kernel(
    const float* __restrict__ Vdst, const float* __restrict__ g_vd,
    const float* __restrict__ b_vd, const float* __restrict__ Wq,
    const float* __restrict__ bq, const float* __restrict__ We) {
    __shared__ float vrow[4][VV];
    __shared__ float vn[4][VV];
    __shared__ float rsum[4][4], rsq[4][4];
    __shared__ float smu[4], srstd[4];

    int grp = threadIdx.x >> 7;
    int tid = threadIdx.x & 127;
    int bd = blockIdx.x * 4 + grp;

    float x = Vdst[bd * VV + tid];
    vrow[grp][tid] = x;

    float s = x, ss = x * x;
    for (int o = 16; o; o >>= 1) {
        s  += __shfl_down_sync(0xffffffffu, s, o);
        ss += __shfl_down_sync(0xffffffffu, ss, o);
    }
    if ((tid & 31) == 0) { rsum[grp][tid >> 5] = s; rsq[grp][tid >> 5] = ss; }
    __syncthreads();
    if (tid == 0) {
        float S = rsum[grp][0] + rsum[grp][1] + rsum[grp][2] + rsum[grp][3];
        float Q = rsq[grp][0] + rsq[grp][1] + rsq[grp][2] + rsq[grp][3];
        float m = S * (1.f / VV);
        float var = Q * (1.f / VV) - m * m;
        smu[grp] = m;
        srstd[grp] = rsqrtf(var + LN_EPS);
    }
    __syncthreads();
    vn[grp][tid] = (x - smu[grp]) * srstd[grp] * g_vd[tid] + b_vd[tid];
    __syncthreads();

    if (tid < 64) {
        float q = bq[tid];
        #pragma unroll 4
        for (int j = 0; j < VV; j++) q += vn[grp][j] * __ldg(Wq + j * 64 + tid);
        g_q[bd * 64 + tid] = fmaxf(q, 0.f);
    } else {
        int t = tid - 64;
        float w = 0.f;
        #pragma unroll 4
        for (int j = 0; j < VV; j++) w += vrow[grp][j] * __ldg(We + (128 + j) * 64 + t);
        g_wd[bd * 64 + t] = w;
    }
}

// ---------------- A_new == 1.0 exactly ----------------
__global__ void fill_a(float* __restrict__ outA) {
    int idx = blockIdx.x * 1024 + threadIdx.x;
    outA[idx] = 1.0f;
}

// ---------------- main fused kernel: one (b, d) per block, 256 s-rows, 2+ CTAs/SM ----------------
// D[256,192] = X[256,64] @ W2[64,192] via fp16 2-term split (x exact to 2^-22, w to 2^-11).
__global__ void __launch_bounds__(256, 2) main_kernel(
    const float* __restrict__ Egl, const float* __restrict__ A,
    const float* __restrict__ be, float* __restrict__ outE) {
    extern __shared__ __align__(16) unsigned char smm[];
    int tid = threadIdx.x;
    int lane = tid & 31, wid = tid >> 5;
    int bx = blockIdx.x;
    int d = bx & 255, b = bx >> 8;
    int bd = b * DD + d;

    float* qs   = (float*)(smm + OFF_QS);
    float* wds  = (float*)(smm + OFF_WDS);
    float* s1k  = (float*)(smm + OFF_S1K);
    float* s2k  = (float*)(smm + OFF_S2K);
    float* s1v  = (float*)(smm + OFF_S1V);
    float* s2v  = (float*)(smm + OFF_S2V);
    float* bes  = (float*)(smm + OFF_BES);
    float* ssum = (float*)(smm + OFF_SSUM);
    float* ssq  = (float*)(smm + OFF_SSQ);
    float* red  = (float*)(smm + OFF_RED);
    float* db   = (float*)(smm + DBX_OFF);
    if (tid < 64) {
        qs[tid]  = g_q[bd * 64 + tid];
        wds[tid] = g_wd[bd * 64 + tid];
        s1k[tid] = g_S1k[tid]; s2k[tid] = g_S2k[tid];
        s1v[tid] = g_S1v[tid]; s2v[tid] = g_S2v[tid];
        bes[tid] = be[tid];
    }

    // stage W2^T fp16 into smem (27648 B)
    {
        const uint4* sh = (const uint4*)g_WTh;
        uint4* dh = (uint4*)(smm + WH_OFF);
        #pragma unroll 4
        for (int i = tid; i < 1728; i += 256) dh[i] = sh[i];
    }

    // ---- chunked X staging (coalesced) + per-chunk fragment pickup ----
    int g = lane >> 2, tc = lane & 3;
    uint32_t ahf[2][4][4], alf[2][4][4];
    int mychunk = wid >> 1;
    #pragma unroll 1
    for (int c = 0; c < 4; c++) {
        #pragma unroll
        for (int it = 0; it < 4; it++) {
            int idx = it * 256 + tid;
            int lrow = idx >> 4;
            int seg = idx & 15;
            int row = c * 64 + lrow;
            float4 u = __ldg((const float4*)(Egl + ((size_t)(b * SS + row) * DD + d) * EE) + seg);
            float ps = u.x + u.y + u.z + u.w;
            float pq = u.x * u.x + u.y * u.y + u.z * u.z + u.w * u.w;
            #pragma unroll
            for (int o = 8; o; o >>= 1) {
                ps += __shfl_xor_sync(0xffffffffu, ps, o);
                pq += __shfl_xor_sync(0xffffffffu, pq, o);
            }
            if ((lane & 15) == 0) { ssum[row] = ps; ssq[row] = pq; }
            float x[4] = {u.x, u.y, u.z, u.w};
            uint32_t hp[2], lp[2];
            #pragma unroll
            for (int t = 0; t < 2; t++) {
                float a0 = x[2 * t], a1 = x[2 * t + 1];
                __half h0 = __float2half_rn(a0), h1 = __float2half_rn(a1);
                __half l0 = __float2half_rn(a0 - __half2float(h0));
                __half l1 = __float2half_rn(a1 - __half2float(h1));
                __half2 ph = __halves2half2(h0, h1);
                __half2 pl = __halves2half2(l0, l1);
                hp[t] = *(uint32_t*)&ph; lp[t] = *(uint32_t*)&pl;
            }
            uint32_t boff = (uint32_t)(lrow * 72 + seg * 4) * 2;
            *(uint2*)(smm + XH_OFF + boff) = make_uint2(hp[0], hp[1]);
            *(uint2*)(smm + XL_OFF + boff) = make_uint2(lp[0], lp[1]);
        }
        __syncthreads();
        if (mychunk == c) {
            int rb = (wid & 1) * 32 + g;
            #pragma unroll
            for (int mt = 0; mt < 2; mt++) {
                int r0 = rb + mt * 16;
                #pragma unroll
                for (int ks = 0; ks < 4; ks++) {
                    int c0 = tc * 2 + 16 * ks;
                    ahf[mt][ks][0] = *(const uint32_t*)(smm + XH_OFF + (r0 * 72 + c0) * 2);
                    ahf[mt][ks][1] = *(const uint32_t*)(smm + XH_OFF + ((r0 + 8) * 72 + c0) * 2);
                    ahf[mt][ks][2] = *(const uint32_t*)(smm + XH_OFF + (r0 * 72 + c0 + 8) * 2);
                    ahf[mt][ks][3] = *(const uint32_t*)(smm + XH_OFF + ((r0 + 8) * 72 + c0 + 8) * 2);
                    alf[mt][ks][0] = *(const uint32_t*)(smm + XL_OFF + (r0 * 72 + c0) * 2);
                    alf[mt][ks][1] = *(const uint32_t*)(smm + XL_OFF + ((r0 + 8) * 72 + c0) * 2);
                    alf[mt][ks][2] = *(const uint32_t*)(smm + XL_OFF + (r0 * 72 + c0 + 8) * 2);
                    alf[mt][ks][3] = *(const uint32_t*)(smm + XL_OFF + ((r0 + 8) * 72 + c0 + 8) * 2);
                }
            }
        }
        __syncthreads();
    }

    // per-thread row r = tid: LN stats
    int r = tid;
    size_t bs = (size_t)(b * SS + r);
    int gbs = b * SS + r;
    float av = __ldg(A + bs * DD + d);
    float mu = (av * g_sv[bs] + ssum[r]) * (1.f / CC);
    float msq = (av * av * g_sq[bs] + ssq[r]) * (1.f / CC);
    float rstd = rsqrtf(msq - mu * mu + LN_EPS);

    float sc[8];
    #pragma unroll
    for (int h = 0; h < 8; h++) sc[h] = 0.f;

    // ---- 6 phases of 32 columns each ----
    #pragma unroll 1
    for (int p = 0; p < 6; p++) {
        // GEMM: cols p*32 .. p*32+31 into db[256][33]
        #pragma unroll 1
        for (int nt = 0; nt < 4; nt++) {
            int n = p * 32 + nt * 8 + g;
            uint32_t bhf[4][2];
            #pragma unroll
            for (int ks = 0; ks < 4; ks++) {
                int kk = tc * 2 + 16 * ks;
                bhf[ks][0] = *(const uint32_t*)(smm + WH_OFF + (n * 72 + kk) * 2);
                bhf[ks][1] = *(const uint32_t*)(smm + WH_OFF + (n * 72 + kk + 8) * 2);
            }
            float a0[2][4], a1[2][4];
            #pragma unroll
            for (int mt = 0; mt < 2; mt++)
                #pragma unroll
                for (int i = 0; i < 4; i++) { a0[mt][i] = 0.f; a1[mt][i] = 0.f; }
            #pragma unroll
            for (int ks = 0; ks < 4; ks++) {
                #pragma unroll
                for (int mt = 0; mt < 2; mt++) {
                    mma16816(a0[mt], ahf[mt][ks], bhf[ks]);
                    mma16816(a1[mt], alf[mt][ks], bhf[ks]);
                }
            }
            #pragma unroll
            for (int mt = 0; mt < 2; mt++) {
                int r0 = wid * 32 + mt * 16 + g;
                int col = nt * 8 + tc * 2;
                db[r0 * 33 + col]           = a0[mt][0] + a1[mt][0];
                db[r0 * 33 + col + 1]       = a0[mt][1] + a1[mt][1];
                db[(r0 + 8) * 33 + col]     = a0[mt][2] + a1[mt][2];
                db[(r0 + 8) * 33 + col + 1] = a0[mt][3] + a1[mt][3];
            }
        }
        __syncthreads();

        // epilogue (coalesced G1T reads)
        if (p < 2) {
            #pragma unroll
            for (int j = 0; j < 32; j++) {
                int jg = p * 32 + j;
                float gv = __ldg(g_G1T + (size_t)jg * (BB * SS) + gbs);
                float yf = av * gv + db[r * 33 + j];
                float kk = fmaxf(rstd * (yf - mu * s1k[jg]) + s2k[jg], 0.f);
                sc[jg >> 3] += qs[jg] * kk;
            }
            if (p == 1) {
                float mx = sc[0] * 0.35355339059327373f;
                #pragma unroll
                for (int h = 0; h < 8; h++) { sc[h] *= 0.35355339059327373f; mx = fmaxf(mx, sc[h]); }
                float sum = 0.f;
                #pragma unroll
                for (int h = 0; h < 8; h++) { sc[h] = __expf(sc[h] - mx); sum += sc[h]; }
                float inv = 1.f / sum;
                #pragma unroll
                for (int h = 0; h < 8; h++) sc[h] *= inv;
            }
            __syncthreads();
        } else if (p < 4) {
            int q = p - 2;
            #pragma unroll
            for (int j = 0; j < 32; j++) {
                int jg = q * 32 + j;
                float gv = __ldg(g_G1T + (size_t)(64 + jg) * (BB * SS) + gbs);
                float yf = av * gv + db[r * 33 + j];
                float vv = fmaxf(rstd * (yf - mu * s1v[jg]) + s2v[jg], 0.f);
                db[r * 33 + j] = sc[jg >> 3] * vv;
            }
            __syncthreads();
            {
                int col = tid & 31, qq = tid >> 5;
                float s = 0.f;
                int rr0 = qq * 32;
                #pragma unroll 8
                for (int rr = rr0; rr < rr0 + 32; rr++) s += db[rr * 33 + col];
                red[qq * 32 + col] = s;
            }
            __syncthreads();
            if (tid < 32) {
                float s = ((red[tid] + red[32 + tid]) + (red[64 + tid] + red[96 + tid]))
                        + ((red[128 + tid] + red[160 + tid]) + (red[192 + tid] + red[224 + tid]));
                g_o[(size_t)bd * 64 + q * 32 + tid] = s;
            }
            __syncthreads();
        } else {
            int q = p - 4;
            #pragma unroll
            for (int j = 0; j < 32; j++) {
                int jg = q * 32 + j;
                float gv = __ldg(g_G1T + (size_t)(128 + jg) * (BB * SS) + gbs);
                float y = av * gv + db[r * 33 + j] + av * wds[jg] + bes[jg];
                db[r * 33 + j] = fmaxf(y, 0.f);
            }
            __syncthreads();
            #pragma unroll 4
            for (int rr = 0; rr < 32; rr++) {
                int row = wid * 32 + rr;
                outE[((size_t)(b * SS + row) * DD + d) * EE + q * 32 + lane] = db[row * 33 + lane];
            }
            if (p == 4) __syncthreads();
        }
    }
}

// ---------------- finalize: V_dst_out = V_dst + relu(o @ Wo + bo) ----------------
__global__ void __launch_bounds__(128) fin_kernel(
    const float* __restrict__ Vdst, const float* __restrict__ Wo,
    const float* __restrict__ bo, float* __restrict__ outV) {
    __shared__ float os[64];
    int bd = blockIdx.x;
    int tid = threadIdx.x;
    if (tid < 64) os[tid] = g_o[(size_t)bd * 64 + tid];
    __syncthreads();
    float a = bo[tid];
    #pragma unroll 4
    for (int t = 0; t < 64; t++) a += os[t] * __ldg(Wo + t * VV + tid);
    outV[bd * VV + tid] = Vdst[bd * VV + tid] + fmaxf(a, 0.f);
}

// ---------------- launch ----------------
extern "C" void kernel_launch(void* const* d_in, const int* in_sizes, int n_in,
                              void* d_out, int out_size) {
    const float* V_src = (const float*)d_in[0];
    const float* V_dst = (const float*)d_in[1];
    const float* E     = (const float*)d_in[2];
    const float* A     = (const float*)d_in[3];
    const float* g_vd  = (const float*)d_in[4];
    const float* b_vd  = (const float*)d_in[5];
    const float* g_in  = (const float*)d_in[6];
    const float* b_in  = (const float*)d_in[7];
    const float* Wq    = (const float*)d_in[8];
    const float* bq    = (const float*)d_in[9];
    const float* Wk    = (const float*)d_in[10];
    const float* bk    = (const float*)d_in[11];
    const float* Wv    = (const float*)d_in[12];
    const float* bv    = (const float*)d_in[13];
    const float* Wo    = (const float*)d_in[14];
    const float* bo    = (const float*)d_in[15];
    const float* We    = (const float*)d_in[16];
    const float* be    = (const float*)d_in[17];
    // d_in[18] = Wa, d_in[19] = ba: unused — softmax over singleton axis is exactly 1.

    float* outV = (float*)d_out;                       // [4,256,128]
    float* outE = outV + BB * DD * VV;                 // [4,256,256,64]
    float* outA = outE + (size_t)BB * SS * DD * EE;    // [4,256,256]

    const int SMEM_G1 = (1024 + 64 * 192) * (int)sizeof(float);
    cudaFuncSetAttribute(main_kernel, cudaFuncAttributeMaxDynamicSharedMemorySize, SMEM_MAIN);
    cudaFuncSetAttribute(g1_kernel, cudaFuncAttributeMaxDynamicSharedMemorySize, SMEM_G1);

    prep_all<<<321, 192>>>(g_in, b_in, Wk, bk, Wv, bv, We);
    g1_kernel<<<BB * SS / 8, 256, SMEM_G1>>>(V_src);
    qwd_kernel<<<BB * DD / 4, 512>>>(V_dst, g_vd, b_vd, Wq, bq, We);
    fill_a<<<(BB * SS * DD) / 1024, 1024>>>(outA);
    main_kernel<<<BB * DD, 256, SMEM_MAIN>>>(E, A, be, outE);
    fin_kernel<<<BB * DD, 128>>>(V_dst, Wo, bo, outV);
}

// round 12
// speedup vs baseline: 1.8104x; 1.0410x over previous
#include <cuda_runtime.h>
#include <cuda_fp16.h>
#include <math.h>
#include <stdint.h>

// Problem constants
#define BB 4
#define SS 256
#define DD 256
#define VV 128
#define EE 64
#define CC 192
#define LN_EPS 1e-3f

// main-kernel smem byte offsets
// W: [192 n][72 k] fp16 (27648 B); two db buffers [256][33] f32 (33792 B each);
// X chunk staging (2 x 9216 B transient) aliased under DB0.
#define WH_OFF  0
#define DB0_OFF 27648
#define DB1_OFF 61440
#define XH_OFF  DB0_OFF
#define XL_OFF  (DB0_OFF + 9216)
#define AUX     95232
#define OFF_QS   (AUX)
#define OFF_WDS  (AUX + 256)
#define OFF_S1K  (AUX + 512)
#define OFF_S2K  (AUX + 768)
#define OFF_S1V  (AUX + 1024)
#define OFF_S2V  (AUX + 1280)
#define OFF_BES  (AUX + 1536)
#define OFF_SSUM (AUX + 1792)
#define OFF_SSQ  (AUX + 2816)
#define OFF_RED  (AUX + 3840)
#define SMEM_MAIN (AUX + 4864)   // 100096 bytes -> 2 CTAs/SM (200 KB < 228 KB)

// ---------------- device scratch ----------------
__device__ __align__(16) float g_Wall[128 * 192];    // rows 0..127 (for g1)
__device__ float g_S1k[64], g_S2k[64], g_S1v[64], g_S2v[64];
__device__ float g_q[BB * DD * 64];
__device__ float g_wd[BB * DD * 64];
__device__ float g_o[BB * DD * 64];
__device__ __align__(16) float g_G1T[192 * BB * SS];  // TRANSPOSED: [n][b*s]
__device__ float g_sv[BB * SS], g_sq[BB * SS];
__device__ __align__(16) __half g_WTh[192 * 72];      // W2^T fp16, [n][k] padded

// ---------------- mma.sync helper (fp16 in, fp32 accum; baseline sm_80+ PTX) ----------------
__device__ __forceinline__ void mma16816(float* c, const uint32_t* a, const uint32_t* b) {
    asm volatile(
        "mma.sync.aligned.m16n8k16.row.col.f32.f16.f16.f32 "
        "{%0,%1,%2,%3}, {%4,%5,%6,%7}, {%8,%9}, {%0,%1,%2,%3};"
        : "+f"(c[0]), "+f"(c[1]), "+f"(c[2]), "+f"(c[3])
        : "r"(a[0]), "r"(a[1]), "r"(a[2]), "r"(a[3]), "r"(b[0]), "r"(b[1]));
}

// GEMM of one 32-col phase into db (no barriers inside)
__device__ __forceinline__ void gemm_phase(
    const unsigned char* smm, float* db, int p, int g, int tc, int wid,
    const uint32_t (&ahf)[2][4][4], const uint32_t (&alf)[2][4][4]) {
    #pragma unroll
    for (int nt = 0; nt < 4; nt++) {
        int n = p * 32 + nt * 8 + g;
        uint32_t bhf[4][2];
        #pragma unroll
        for (int ks = 0; ks < 4; ks++) {
            int kk = tc * 2 + 16 * ks;
            bhf[ks][0] = *(const uint32_t*)(smm + WH_OFF + (n * 72 + kk) * 2);
            bhf[ks][1] = *(const uint32_t*)(smm + WH_OFF + (n * 72 + kk + 8) * 2);
        }
        float a0[2][4], a1[2][4];
        #pragma unroll
        for (int mt = 0; mt < 2; mt++)
            #pragma unroll
            for (int i = 0; i < 4; i++) { a0[mt][i] = 0.f; a1[mt][i] = 0.f; }
        #pragma unroll
        for (int ks = 0; ks < 4; ks++) {
            #pragma unroll
            for (int mt = 0; mt < 2; mt++) {
                mma16816(a0[mt], ahf[mt][ks], bhf[ks]);
                mma16816(a1[mt], alf[mt][ks], bhf[ks]);
            }
        }
        #pragma unroll
        for (int mt = 0; mt < 2; mt++) {
            int r0 = wid * 32 + mt * 16 + g;
            int col = nt * 8 + tc * 2;
            db[r0 * 33 + col]           = a0[mt][0] + a1[mt][0];
            db[r0 * 33 + col + 1]       = a0[mt][1] + a1[mt][1];
            db[(r0 + 8) * 33 + col]     = a0[mt][2] + a1[mt][2];
            db[(r0 + 8) * 33 + col + 1] = a0[mt][3] + a1[mt][3];
        }
    }
}

// ---------------- prep: all weight preprocessing in one kernel ----------------
__global__ void prep_all(const float* __restrict__ g_in, const float* __restrict__ b_in,
                         const float* __restrict__ Wk, const float* __restrict__ bk,
                         const float* __restrict__ Wv, const float* __restrict__ bv,
                         const float* __restrict__ We) {
    int bid = blockIdx.x;
    int tid = threadIdx.x;   // 192
    if (bid < 128) {
        int c = bid, j = tid;
        float g = g_in[c];
        float val;
        if (j < 64)        val = g * Wk[c * 64 + j];
        else if (j < 128)  val = g * Wv[c * 64 + (j - 64)];
        else               val = We[c * 64 + (j - 128)];       // c < 128
        g_Wall[c * 192 + j] = val;
    } else if (bid < 320) {
        int n = bid - 128;
        if (tid < 64) {
            int k = tid;
            int c = 128 + k;
            float g = g_in[c];
            float w;
            if (n < 64)        w = g * Wk[c * 64 + n];
            else if (n < 128)  w = g * Wv[c * 64 + (n - 64)];
            else               w = We[(c + 128) * 64 + (n - 128)];
            g_WTh[n * 72 + k] = __float2half_rn(w);
            if (k >= 56) g_WTh[n * 72 + 8 + k] = __float2half_rn(0.f);
        }
    } else {
        if (tid < 64) {
            int j = tid;
            float s1 = 0.f, s2 = 0.f;
            for (int c = 0; c < CC; c++) {
                float w = Wk[c * 64 + j];
                s1 += g_in[c] * w;
                s2 += b_in[c] * w;
            }
            g_S1k[j] = s1;
            g_S2k[j] = s2 + bk[j];
        } else if (tid < 128) {
            int j = tid - 64;
            float s1 = 0.f, s2 = 0.f;
            for (int c = 0; c < CC; c++) {
                float w = Wv[c * 64 + j];
                s1 += g_in[c] * w;
                s2 += b_in[c] * w;
            }
            g_S1v[j] = s1;
            g_S2v[j] = s2 + bv[j];
        }
    }
}

// ---------------- G1T[n][bs] = (Vsrc @ Wall[0:128,:])^T  (+ row sums for LN) ----------------
__global__ void __launch_bounds__(256) g1_kernel(const float* __restrict__ Vsrc) {
    extern __shared__ float smf[];
    float* xt = smf;           // [128 c][8 r]
    float* ws = smf + 1024;    // [64 c][192 n]
    int bs0 = blockIdx.x * 8;
    int tid = threadIdx.x;
    int tx = tid & 31, ty = tid >> 5;

    for (int idx = tid; idx < 1024; idx += 256) {
        int c = idx & 127, r = idx >> 7;
        xt[c * 8 + r] = Vsrc[(bs0 + r) * VV + c];
    }
    __syncthreads();
    if (tid < 8) {
        float s = 0.f, ss = 0.f;
        for (int c = 0; c < VV; c++) {
            float x = xt[c * 8 + tid];
            s += x; ss += x * x;
        }
        g_sv[bs0 + tid] = s;
        g_sq[bs0 + tid] = ss;
    }

    float acc[6];
    #pragma unroll
    for (int i = 0; i < 6; i++) acc[i] = 0.f;

    for (int h = 0; h < 2; h++) {
        __syncthreads();
        const float4* src = (const float4*)(g_Wall + h * 64 * 192);
        float4* dst = (float4*)ws;
        for (int idx = tid; idx < 3072; idx += 256) dst[idx] = src[idx];
        __syncthreads();
        #pragma unroll 4
        for (int c = 0; c < 64; c++) {
            float x = xt[(h * 64 + c) * 8 + ty];
            const float* wr = ws + c * 192 + tx;
            #pragma unroll
            for (int i = 0; i < 6; i++) acc[i] = fmaf(x, wr[i * 32], acc[i]);
        }
    }
    #pragma unroll
    for (int i = 0; i < 6; i++)
        g_G1T[(size_t)(tx + 32 * i) * (BB * SS) + bs0 + ty] = acc[i];
}

// ---------------- per-(b,d): LN(V_dst) -> q, and wd GEMV (4 bd per block) ----------------
__global__ void __launch_bounds__(512) qwd_kernel(
    const float* __restrict__ Vdst, const float* __restrict__ g_vd,
    const float* __restrict__ b_vd, const float* __restrict__ Wq,
    const float* __restrict__ bq, const float* __restrict__ We) {
    __shared__ float vrow[4][VV];
    __shared__ float vn[4][VV];
    __shared__ float rsum[4][4], rsq[4][4];
    __shared__ float smu[4], srstd[4];

    int grp = threadIdx.x >> 7;
    int tid = threadIdx.x & 127;
    int bd = blockIdx.x * 4 + grp;

    float x = Vdst[bd * VV + tid];
    vrow[grp][tid] = x;

    float s = x, ss = x * x;
    for (int o = 16; o; o >>= 1) {
        s  += __shfl_down_sync(0xffffffffu, s, o);
        ss += __shfl_down_sync(0xffffffffu, ss, o);
    }
    if ((tid & 31) == 0) { rsum[grp][tid >> 5] = s; rsq[grp][tid >> 5] = ss; }
    __syncthreads();
    if (tid == 0) {
        float S = rsum[grp][0] + rsum[grp][1] + rsum[grp][2] + rsum[grp][3];
        float Q = rsq[grp][0] + rsq[grp][1] + rsq[grp][2] + rsq[grp][3];
        float m = S * (1.f / VV);
        float var = Q * (1.f / VV) - m * m;
        smu[grp] = m;
        srstd[grp] = rsqrtf(var + LN_EPS);
    }
    __syncthreads();
    vn[grp][tid] = (x - smu[grp]) * srstd[grp] * g_vd[tid] + b_vd[tid];
    __syncthreads();

    if (tid < 64) {
        float q = bq[tid];
        #pragma unroll 4
        for (int j = 0; j < VV; j++) q += vn[grp][j] * __ldg(Wq + j * 64 + tid);
        g_q[bd * 64 + tid] = fmaxf(q, 0.f);
    } else {
        int t = tid - 64;
        float w = 0.f;
        #pragma unroll 4
        for (int j = 0; j < VV; j++) w += vrow[grp][j] * __ldg(We + (128 + j) * 64 + t);
        g_wd[bd * 64 + t] = w;
    }
}

// ---------------- main fused kernel: one (b, d) per block, double-buffered pipeline ----------------
__global__ void __launch_bounds__(256, 2) main_kernel(
    const float* __restrict__ Egl, const float* __restrict__ A,
    const float* __restrict__ be, float* __restrict__ outE) {
    extern __shared__ __align__(16) unsigned char smm[];
    int tid = threadIdx.x;
    int lane = tid & 31, wid = tid >> 5;
    int bx = blockIdx.x;
    int d = bx & 255, b = bx >> 8;
    int bd = b * DD + d;

    float* qs   = (float*)(smm + OFF_QS);
    float* wds  = (float*)(smm + OFF_WDS);
    float* s1k  = (float*)(smm + OFF_S1K);
    float* s2k  = (float*)(smm + OFF_S2K);
    float* s1v  = (float*)(smm + OFF_S1V);
    float* s2v  = (float*)(smm + OFF_S2V);
    float* bes  = (float*)(smm + OFF_BES);
    float* ssum = (float*)(smm + OFF_SSUM);
    float* ssq  = (float*)(smm + OFF_SSQ);
    float* red  = (float*)(smm + OFF_RED);
    float* db0  = (float*)(smm + DB0_OFF);
    float* db1  = (float*)(smm + DB1_OFF);
    if (tid < 64) {
        qs[tid]  = g_q[bd * 64 + tid];
        wds[tid] = g_wd[bd * 64 + tid];
        s1k[tid] = g_S1k[tid]; s2k[tid] = g_S2k[tid];
        s1v[tid] = g_S1v[tid]; s2v[tid] = g_S2v[tid];
        bes[tid] = be[tid];
    }

    // stage W2^T fp16 into smem (27648 B)
    {
        const uint4* sh = (const uint4*)g_WTh;
        uint4* dh = (uint4*)(smm + WH_OFF);
        #pragma unroll 4
        for (int i = tid; i < 1728; i += 256) dh[i] = sh[i];
    }

    // ---- chunked X staging (coalesced) + per-chunk fragment pickup ----
    int g = lane >> 2, tc = lane & 3;
    uint32_t ahf[2][4][4], alf[2][4][4];
    int mychunk = wid >> 1;
    #pragma unroll 1
    for (int c = 0; c < 4; c++) {
        #pragma unroll
        for (int it = 0; it < 4; it++) {
            int idx = it * 256 + tid;
            int lrow = idx >> 4;
            int seg = idx & 15;
            int row = c * 64 + lrow;
            float4 u = __ldg((const float4*)(Egl + ((size_t)(b * SS + row) * DD + d) * EE) + seg);
            float ps = u.x + u.y + u.z + u.w;
            float pq = u.x * u.x + u.y * u.y + u.z * u.z + u.w * u.w;
            #pragma unroll
            for (int o = 8; o; o >>= 1) {
                ps += __shfl_xor_sync(0xffffffffu, ps, o);
                pq += __shfl_xor_sync(0xffffffffu, pq, o);
            }
            if ((lane & 15) == 0) { ssum[row] = ps; ssq[row] = pq; }
            float x[4] = {u.x, u.y, u.z, u.w};
            uint32_t hp[2], lp[2];
            #pragma unroll
            for (int t = 0; t < 2; t++) {
                float a0 = x[2 * t], a1 = x[2 * t + 1];
                __half h0 = __float2half_rn(a0), h1 = __float2half_rn(a1);
                __half l0 = __float2half_rn(a0 - __half2float(h0));
                __half l1 = __float2half_rn(a1 - __half2float(h1));
                __half2 ph = __halves2half2(h0, h1);
                __half2 pl = __halves2half2(l0, l1);
                hp[t] = *(uint32_t*)&ph; lp[t] = *(uint32_t*)&pl;
            }
            uint32_t boff = (uint32_t)(lrow * 72 + seg * 4) * 2;
            *(uint2*)(smm + XH_OFF + boff) = make_uint2(hp[0], hp[1]);
            *(uint2*)(smm + XL_OFF + boff) = make_uint2(lp[0], lp[1]);
        }
        __syncthreads();
        if (mychunk == c) {
            int rb = (wid & 1) * 32 + g;
            #pragma unroll
            for (int mt = 0; mt < 2; mt++) {
                int r0 = rb + mt * 16;
                #pragma unroll
                for (int ks = 0; ks < 4; ks++) {
                    int c0 = tc * 2 + 16 * ks;
                    ahf[mt][ks][0] = *(const uint32_t*)(smm + XH_OFF + (r0 * 72 + c0) * 2);
                    ahf[mt][ks][1] = *(const uint32_t*)(smm + XH_OFF + ((r0 + 8) * 72 + c0) * 2);
                    ahf[mt][ks][2] = *(const uint32_t*)(smm + XH_OFF + (r0 * 72 + c0 + 8) * 2);
                    ahf[mt][ks][3] = *(const uint32_t*)(smm + XH_OFF + ((r0 + 8) * 72 + c0 + 8) * 2);
                    alf[mt][ks][0] = *(const uint32_t*)(smm + XL_OFF + (r0 * 72 + c0) * 2);
                    alf[mt][ks][1] = *(const uint32_t*)(smm + XL_OFF + ((r0 + 8) * 72 + c0) * 2);
                    alf[mt][ks][2] = *(const uint32_t*)(smm + XL_OFF + (r0 * 72 + c0 + 8) * 2);
                    alf[mt][ks][3] = *(const uint32_t*)(smm + XL_OFF + ((r0 + 8) * 72 + c0 + 8) * 2);
                }
            }
        }
        __syncthreads();
    }

    // per-thread row r = tid: LN stats
    int r = tid;
    size_t bs = (size_t)(b * SS + r);
    int gbs = b * SS + r;
    float av = __ldg(A + bs * DD + d);
    float mu = (av * g_sv[bs] + ssum[r]) * (1.f / CC);
    float msq = (av * av * g_sq[bs] + ssq[r]) * (1.f / CC);
    float rstd = rsqrtf(msq - mu * mu + LN_EPS);

    float sc[8];
    #pragma unroll
    for (int h = 0; h < 8; h++) sc[h] = 0.f;

    // ---- pipelined phases: GEMM(p+1) issued before epilogue(p) ----
    gemm_phase(smm, db0, 0, g, tc, wid, ahf, alf);
    __syncthreads();

    #pragma unroll 1
    for (int p = 0; p < 6; p++) {
        if (p < 5) gemm_phase(smm, (p & 1) ? db0 : db1, p + 1, g, tc, wid, ahf, alf);
        float* db = (p & 1) ? db1 : db0;

        if (p < 2) {
            #pragma unroll
            for (int j = 0; j < 32; j++) {
                int jg = p * 32 + j;
                float gv = __ldg(g_G1T + (size_t)jg * (BB * SS) + gbs);
                float yf = av * gv + db[r * 33 + j];
                float kk = fmaxf(rstd * (yf - mu * s1k[jg]) + s2k[jg], 0.f);
                sc[jg >> 3] += qs[jg] * kk;
            }
            if (p == 1) {
                float mx = sc[0] * 0.35355339059327373f;
                #pragma unroll
                for (int h = 0; h < 8; h++) { sc[h] *= 0.35355339059327373f; mx = fmaxf(mx, sc[h]); }
                float sum = 0.f;
                #pragma unroll
                for (int h = 0; h < 8; h++) { sc[h] = __expf(sc[h] - mx); sum += sc[h]; }
                float inv = 1.f / sum;
                #pragma unroll
                for (int h = 0; h < 8; h++) sc[h] *= inv;
            }
            __syncthreads();
        } else if (p < 4) {
            int q = p - 2;
            #pragma unroll
            for (int j = 0; j < 32; j++) {
                int jg = q * 32 + j;
                float gv = __ldg(g_G1T + (size_t)(64 + jg) * (BB * SS) + gbs);
                float yf = av * gv + db[r * 33 + j];
                float vv = fmaxf(rstd * (yf - mu * s1v[jg]) + s2v[jg], 0.f);
                db[r * 33 + j] = sc[jg >> 3] * vv;
            }
            __syncthreads();
            {
                int col = tid & 31, qq = tid >> 5;
                float s = 0.f;
                int rr0 = qq * 32;
                #pragma unroll 8
                for (int rr = rr0; rr < rr0 + 32; rr++) s += db[rr * 33 + col];
                red[qq * 32 + col] = s;
            }
            __syncthreads();
            if (tid < 32) {
                float s = ((red[tid] + red[32 + tid]) + (red[64 + tid] + red[96 + tid]))
                        + ((red[128 + tid] + red[160 + tid]) + (red[192 + tid] + red[224 + tid]));
                g_o[(size_t)bd * 64 + q * 32 + tid] = s;
            }
            __syncthreads();
        } else {
            int q = p - 4;
            #pragma unroll
            for (int j = 0; j < 32; j++) {
                int jg = q * 32 + j;
                float gv = __ldg(g_G1T + (size_t)(128 + jg) * (BB * SS) + gbs);
                float y = av * gv + db[r * 33 + j] + av * wds[jg] + bes[jg];
                db[r * 33 + j] = fmaxf(y, 0.f);
            }
            __syncthreads();
            #pragma unroll 4
            for (int rr = 0; rr < 32; rr++) {
                int row = wid * 32 + rr;
                outE[((size_t)(b * SS + row) * DD + d) * EE + q * 32 + lane] = db[row * 33 + lane];
            }
            if (p == 4) __syncthreads();
        }
    }
}

// ---------------- finalize: V_dst_out = V_dst + relu(o @ Wo + bo); also outA = 1 ----------------
__global__ void __launch_bounds__(128) fin_kernel(
    const float* __restrict__ Vdst, const float* __restrict__ Wo,
    const float* __restrict__ bo, float* __restrict__ outV,
    float* __restrict__ outA) {
    __shared__ float os[64];
    int bd = blockIdx.x;
    int tid = threadIdx.x;
    if (tid < 64) os[tid] = g_o[(size_t)bd * 64 + tid];
    // A_new == 1.0 exactly (softmax over singleton axis)
    outA[bd * 256 + tid] = 1.0f;
    outA[bd * 256 + 128 + tid] = 1.0f;
    __syncthreads();
    float a = bo[tid];
    #pragma unroll 4
    for (int t = 0; t < 64; t++) a += os[t] * __ldg(Wo + t * VV + tid);
    outV[bd * VV + tid] = Vdst[bd * VV + tid] + fmaxf(a, 0.f);
}

// ---------------- launch ----------------
extern "C" void kernel_launch(void* const* d_in, const int* in_sizes, int n_in,
                              void* d_out, int out_size) {
    const float* V_src = (const float*)d_in[0];
    const float* V_dst = (const float*)d_in[1];
    const float* E     = (const float*)d_in[2];
    const float* A     = (const float*)d_in[3];
    const float* g_vd  = (const float*)d_in[4];
    const float* b_vd  = (const float*)d_in[5];
    const float* g_in  = (const float*)d_in[6];
    const float* b_in  = (const float*)d_in[7];
    const float* Wq    = (const float*)d_in[8];
    const float* bq    = (const float*)d_in[9];
    const float* Wk    = (const float*)d_in[10];
    const float* bk    = (const float*)d_in[11];
    const float* Wv    = (const float*)d_in[12];
    const float* bv    = (const float*)d_in[13];
    const float* Wo    = (const float*)d_in[14];
    const float* bo    = (const float*)d_in[15];
    const float* We    = (const float*)d_in[16];
    const float* be    = (const float*)d_in[17];
    // d_in[18] = Wa, d_in[19] = ba: unused — softmax over singleton axis is exactly 1.

    float* outV = (float*)d_out;                       // [4,256,128]
    float* outE = outV + BB * DD * VV;                 // [4,256,256,64]
    float* outA = outE + (size_t)BB * SS * DD * EE;    // [4,256,256]

    const int SMEM_G1 = (1024 + 64 * 192) * (int)sizeof(float);
    cudaFuncSetAttribute(main_kernel, cudaFuncAttributeMaxDynamicSharedMemorySize, SMEM_MAIN);
    cudaFuncSetAttribute(g1_kernel, cudaFuncAttributeMaxDynamicSharedMemorySize, SMEM_G1);

    prep_all<<<321, 192>>>(g_in, b_in, Wk, bk, Wv, bv, We);
    g1_kernel<<<BB * SS / 8, 256, SMEM_G1>>>(V_src);
    qwd_kernel<<<BB * DD / 4, 512>>>(V_dst, g_vd, b_vd, Wq, bq, We);
    main_kernel<<<BB * DD, 256, SMEM_MAIN>>>(E, A, be, outE);
    fin_kernel<<<BB * DD, 128>>>(V_dst, Wo, bo, outV, outA);
}

// round 13
// speedup vs baseline: 1.8921x; 1.0452x over previous
#include <cuda_runtime.h>
#include <cuda_fp16.h>
#include <math.h>
#include <stdint.h>

// Problem constants
#define BB 4
#define SS 256
#define DD 256
#define VV 128
#define EE 64
#define CC 192
#define LN_EPS 1e-3f

// main-kernel smem byte offsets
// W: [192 n][72 k] fp16 (27648 B); two db buffers [256][33] f32 (33792 B each);
// X hi staging (9216 B transient) aliased under DB0.
#define WH_OFF  0
#define DB0_OFF 27648
#define DB1_OFF 61440
#define XH_OFF  DB0_OFF
#define AUX     95232
#define OFF_QS   (AUX)
#define OFF_WDS  (AUX + 256)
#define OFF_S1K  (AUX + 512)
#define OFF_S2K  (AUX + 768)
#define OFF_S1V  (AUX + 1024)
#define OFF_S2V  (AUX + 1280)
#define OFF_BES  (AUX + 1536)
#define OFF_SSUM (AUX + 1792)
#define OFF_SSQ  (AUX + 2816)
#define OFF_RED  (AUX + 3840)
#define SMEM_MAIN (AUX + 4864)   // 100096 bytes -> 2 CTAs/SM

// ---------------- device scratch ----------------
__device__ __align__(16) float g_Wall[128 * 192];    // rows 0..127 (for g1)
__device__ float g_S1k[64], g_S2k[64], g_S1v[64], g_S2v[64];
__device__ float g_q[BB * DD * 64];
__device__ float g_wd[BB * DD * 64];
__device__ float g_o[BB * DD * 64];
__device__ __align__(16) float g_G1T[192 * BB * SS];  // TRANSPOSED: [n][b*s]
__device__ float g_sv[BB * SS], g_sq[BB * SS];
__device__ __align__(16) __half g_WTh[192 * 72];      // W2^T fp16, [n][k] padded

// ---------------- mma.sync helper (fp16 in, fp32 accum; baseline sm_80+ PTX) ----------------
__device__ __forceinline__ void mma16816(float* c, const uint32_t* a, const uint32_t* b) {
    asm volatile(
        "mma.sync.aligned.m16n8k16.row.col.f32.f16.f16.f32 "
        "{%0,%1,%2,%3}, {%4,%5,%6,%7}, {%8,%9}, {%0,%1,%2,%3};"
        : "+f"(c[0]), "+f"(c[1]), "+f"(c[2]), "+f"(c[3])
        : "r"(a[0]), "r"(a[1]), "r"(a[2]), "r"(a[3]), "r"(b[0]), "r"(b[1]));
}

// GEMM of one 32-col phase into db (no barriers inside); pure fp16 hi path
__device__ __forceinline__ void gemm_phase(
    const unsigned char* smm, float* db, int p, int g, int tc, int wid,
    const uint32_t (&ahf)[2][4][4]) {
    #pragma unroll
    for (int nt = 0; nt < 4; nt++) {
        int n = p * 32 + nt * 8 + g;
        uint32_t bhf[4][2];
        #pragma unroll
        for (int ks = 0; ks < 4; ks++) {
            int kk = tc * 2 + 16 * ks;
            bhf[ks][0] = *(const uint32_t*)(smm + WH_OFF + (n * 72 + kk) * 2);
            bhf[ks][1] = *(const uint32_t*)(smm + WH_OFF + (n * 72 + kk + 8) * 2);
        }
        float a0[2][4];
        #pragma unroll
        for (int mt = 0; mt < 2; mt++)
            #pragma unroll
            for (int i = 0; i < 4; i++) a0[mt][i] = 0.f;
        #pragma unroll
        for (int ks = 0; ks < 4; ks++) {
            #pragma unroll
            for (int mt = 0; mt < 2; mt++)
                mma16816(a0[mt], ahf[mt][ks], bhf[ks]);
        }
        #pragma unroll
        for (int mt = 0; mt < 2; mt++) {
            int r0 = wid * 32 + mt * 16 + g;
            int col = nt * 8 + tc * 2;
            db[r0 * 33 + col]           = a0[mt][0];
            db[r0 * 33 + col + 1]       = a0[mt][1];
            db[(r0 + 8) * 33 + col]     = a0[mt][2];
            db[(r0 + 8) * 33 + col + 1] = a0[mt][3];
        }
    }
}

// ---------------- prep: all weight preprocessing in one kernel ----------------
__global__ void prep_all(const float* __restrict__ g_in, const float* __restrict__ b_in,
                         const float* __restrict__ Wk, const float* __restrict__ bk,
                         const float* __restrict__ Wv, const float* __restrict__ bv,
                         const float* __restrict__ We) {
    int bid = blockIdx.x;
    int tid = threadIdx.x;   // 192
    if (bid < 128) {
        int c = bid, j = tid;
        float g = g_in[c];
        float val;
        if (j < 64)        val = g * Wk[c * 64 + j];
        else if (j < 128)  val = g * Wv[c * 64 + (j - 64)];
        else               val = We[c * 64 + (j - 128)];       // c < 128
        g_Wall[c * 192 + j] = val;
    } else if (bid < 320) {
        int n = bid - 128;
        if (tid < 64) {
            int k = tid;
            int c = 128 + k;
            float g = g_in[c];
            float w;
            if (n < 64)        w = g * Wk[c * 64 + n];
            else if (n < 128)  w = g * Wv[c * 64 + (n - 64)];
            else               w = We[(c + 128) * 64 + (n - 128)];
            g_WTh[n * 72 + k] = __float2half_rn(w);
            if (k >= 56) g_WTh[n * 72 + 8 + k] = __float2half_rn(0.f);
        }
    } else {
        if (tid < 64) {
            int j = tid;
            float s1 = 0.f, s2 = 0.f;
            for (int c = 0; c < CC; c++) {
                float w = Wk[c * 64 + j];
                s1 += g_in[c] * w;
                s2 += b_in[c] * w;
            }
            g_S1k[j] = s1;
            g_S2k[j] = s2 + bk[j];
        } else if (tid < 128) {
            int j = tid - 64;
            float s1 = 0.f, s2 = 0.f;
            for (int c = 0; c < CC; c++) {
                float w = Wv[c * 64 + j];
                s1 += g_in[c] * w;
                s2 += b_in[c] * w;
            }
            g_S1v[j] = s1;
            g_S2v[j] = s2 + bv[j];
        }
    }
}

// ---------------- G1T[n][bs] = (Vsrc @ Wall[0:128,:])^T  (+ row sums for LN) ----------------
__global__ void __launch_bounds__(256) g1_kernel(const float* __restrict__ Vsrc) {
    extern __shared__ float smf[];
    float* xt = smf;           // [128 c][8 r]
    float* ws = smf + 1024;    // [64 c][192 n]
    int bs0 = blockIdx.x * 8;
    int tid = threadIdx.x;
    int tx = tid & 31, ty = tid >> 5;

    for (int idx = tid; idx < 1024; idx += 256) {
        int c = idx & 127, r = idx >> 7;
        xt[c * 8 + r] = Vsrc[(bs0 + r) * VV + c];
    }
    __syncthreads();
    if (tid < 8) {
        float s = 0.f, ss = 0.f;
        for (int c = 0; c < VV; c++) {
            float x = xt[c * 8 + tid];
            s += x; ss += x * x;
        }
        g_sv[bs0 + tid] = s;
        g_sq[bs0 + tid] = ss;
    }

    float acc[6];
    #pragma unroll
    for (int i = 0; i < 6; i++) acc[i] = 0.f;

    for (int h = 0; h < 2; h++) {
        __syncthreads();
        const float4* src = (const float4*)(g_Wall + h * 64 * 192);
        float4* dst = (float4*)ws;
        for (int idx = tid; idx < 3072; idx += 256) dst[idx] = src[idx];
        __syncthreads();
        #pragma unroll 4
        for (int c = 0; c < 64; c++) {
            float x = xt[(h * 64 + c) * 8 + ty];
            const float* wr = ws + c * 192 + tx;
            #pragma unroll
            for (int i = 0; i < 6; i++) acc[i] = fmaf(x, wr[i * 32], acc[i]);
        }
    }
    #pragma unroll
    for (int i = 0; i < 6; i++)
        g_G1T[(size_t)(tx + 32 * i) * (BB * SS) + bs0 + ty] = acc[i];
}

// ---------------- per-(b,d): LN(V_dst) -> q, and wd GEMV (4 bd per block) ----------------
__global__ void __launch_bounds__(512) qwd_kernel(
    const float* __restrict__ Vdst, const float* __restrict__ g_vd,
    const float* __restrict__ b_vd, const float* __restrict__ Wq,
    const float* __restrict__ bq, const float* __restrict__ We) {
    __shared__ float vrow[4][VV];
    __shared__ float vn[4][VV];
    __shared__ float rsum[4][4], rsq[4][4];
    __shared__ float smu[4], srstd[4];

    int grp = threadIdx.x >> 7;
    int tid = threadIdx.x & 127;
    int bd = blockIdx.x * 4 + grp;

    float x = Vdst[bd * VV + tid];
    vrow[grp][tid] = x;

    float s = x, ss = x * x;
    for (int o = 16; o; o >>= 1) {
        s  += __shfl_down_sync(0xffffffffu, s, o);
        ss += __shfl_down_sync(0xffffffffu, ss, o);
    }
    if ((tid & 31) == 0) { rsum[grp][tid >> 5] = s; rsq[grp][tid >> 5] = ss; }
    __syncthreads();
    if (tid == 0) {
        float S = rsum[grp][0] + rsum[grp][1] + rsum[grp][2] + rsum[grp][3];
        float Q = rsq[grp][0] + rsq[grp][1] + rsq[grp][2] + rsq[grp][3];
        float m = S * (1.f / VV);
        float var = Q * (1.f / VV) - m * m;
        smu[grp] = m;
        srstd[grp] = rsqrtf(var + LN_EPS);
    }
    __syncthreads();
    vn[grp][tid] = (x - smu[grp]) * srstd[grp] * g_vd[tid] + b_vd[tid];
    __syncthreads();

    if (tid < 64) {
        float q = bq[tid];
        #pragma unroll 4
        for (int j = 0; j < VV; j++) q += vn[grp][j] * __ldg(Wq + j * 64 + tid);
        g_q[bd * 64 + tid] = fmaxf(q, 0.f);
    } else {
        int t = tid - 64;
        float w = 0.f;
        #pragma unroll 4
        for (int j = 0; j < VV; j++) w += vrow[grp][j] * __ldg(We + (128 + j) * 64 + t);
        g_wd[bd * 64 + t] = w;
    }
}

// ---------------- main fused kernel: one (b, d) per block, double-buffered pipeline ----------------
__global__ void __launch_bounds__(256, 2) main_kernel(
    const float* __restrict__ Egl, const float* __restrict__ A,
    const float* __restrict__ be, float* __restrict__ outE) {
    extern __shared__ __align__(16) unsigned char smm[];
    int tid = threadIdx.x;
    int lane = tid & 31, wid = tid >> 5;
    int bx = blockIdx.x;
    int d = bx & 255, b = bx >> 8;
    int bd = b * DD + d;

    float* qs   = (float*)(smm + OFF_QS);
    float* wds  = (float*)(smm + OFF_WDS);
    float* s1k  = (float*)(smm + OFF_S1K);
    float* s2k  = (float*)(smm + OFF_S2K);
    float* s1v  = (float*)(smm + OFF_S1V);
    float* s2v  = (float*)(smm + OFF_S2V);
    float* bes  = (float*)(smm + OFF_BES);
    float* ssum = (float*)(smm + OFF_SSUM);
    float* ssq  = (float*)(smm + OFF_SSQ);
    float* red  = (float*)(smm + OFF_RED);
    float* db0  = (float*)(smm + DB0_OFF);
    float* db1  = (float*)(smm + DB1_OFF);
    if (tid < 64) {
        qs[tid]  = g_q[bd * 64 + tid];
        wds[tid] = g_wd[bd * 64 + tid];
        s1k[tid] = g_S1k[tid]; s2k[tid] = g_S2k[tid];
        s1v[tid] = g_S1v[tid]; s2v[tid] = g_S2v[tid];
        bes[tid] = be[tid];
    }

    // stage W2^T fp16 into smem (27648 B)
    {
        const uint4* sh = (const uint4*)g_WTh;
        uint4* dh = (uint4*)(smm + WH_OFF);
        #pragma unroll 4
        for (int i = tid; i < 1728; i += 256) dh[i] = sh[i];
    }

    // ---- chunked X staging (coalesced, fp16 hi only) + per-chunk fragment pickup ----
    int g = lane >> 2, tc = lane & 3;
    uint32_t ahf[2][4][4];
    int mychunk = wid >> 1;
    #pragma unroll 1
    for (int c = 0; c < 4; c++) {
        #pragma unroll
        for (int it = 0; it < 4; it++) {
            int idx = it * 256 + tid;
            int lrow = idx >> 4;
            int seg = idx & 15;
            int row = c * 64 + lrow;
            float4 u = __ldg((const float4*)(Egl + ((size_t)(b * SS + row) * DD + d) * EE) + seg);
            float ps = u.x + u.y + u.z + u.w;
            float pq = u.x * u.x + u.y * u.y + u.z * u.z + u.w * u.w;
            #pragma unroll
            for (int o = 8; o; o >>= 1) {
                ps += __shfl_xor_sync(0xffffffffu, ps, o);
                pq += __shfl_xor_sync(0xffffffffu, pq, o);
            }
            if ((lane & 15) == 0) { ssum[row] = ps; ssq[row] = pq; }
            __half2 ph0 = __halves2half2(__float2half_rn(u.x), __float2half_rn(u.y));
            __half2 ph1 = __halves2half2(__float2half_rn(u.z), __float2half_rn(u.w));
            uint32_t boff = (uint32_t)(lrow * 72 + seg * 4) * 2;
            *(uint2*)(smm + XH_OFF + boff) = make_uint2(*(uint32_t*)&ph0, *(uint32_t*)&ph1);
        }
        __syncthreads();
        if (mychunk == c) {
            int rb = (wid & 1) * 32 + g;
            #pragma unroll
            for (int mt = 0; mt < 2; mt++) {
                int r0 = rb + mt * 16;
                #pragma unroll
                for (int ks = 0; ks < 4; ks++) {
                    int c0 = tc * 2 + 16 * ks;
                    ahf[mt][ks][0] = *(const uint32_t*)(smm + XH_OFF + (r0 * 72 + c0) * 2);
                    ahf[mt][ks][1] = *(const uint32_t*)(smm + XH_OFF + ((r0 + 8) * 72 + c0) * 2);
                    ahf[mt][ks][2] = *(const uint32_t*)(smm + XH_OFF + (r0 * 72 + c0 + 8) * 2);
                    ahf[mt][ks][3] = *(const uint32_t*)(smm + XH_OFF + ((r0 + 8) * 72 + c0 + 8) * 2);
                }
            }
        }
        __syncthreads();
    }

    // per-thread row r = tid: LN stats
    int r = tid;
    size_t bs = (size_t)(b * SS + r);
    int gbs = b * SS + r;
    float av = __ldg(A + bs * DD + d);
    float mu = (av * g_sv[bs] + ssum[r]) * (1.f / CC);
    float msq = (av * av * g_sq[bs] + ssq[r]) * (1.f / CC);
    float rstd = rsqrtf(msq - mu * mu + LN_EPS);

    float sc[8];
    #pragma unroll
    for (int h = 0; h < 8; h++) sc[h] = 0.f;

    // ---- pipelined phases: GEMM(p+1) issued before epilogue(p) ----
    gemm_phase(smm, db0, 0, g, tc, wid, ahf);
    __syncthreads();

    #pragma unroll 1
    for (int p = 0; p < 6; p++) {
        if (p < 5) gemm_phase(smm, (p & 1) ? db0 : db1, p + 1, g, tc, wid, ahf);
        float* db = (p & 1) ? db1 : db0;

        if (p < 2) {
            #pragma unroll
            for (int j = 0; j < 32; j++) {
                int jg = p * 32 + j;
                float gv = __ldg(g_G1T + (size_t)jg * (BB * SS) + gbs);
                float yf = av * gv + db[r * 33 + j];
                float kk = fmaxf(rstd * (yf - mu * s1k[jg]) + s2k[jg], 0.f);
                sc[jg >> 3] += qs[jg] * kk;
            }
            if (p == 1) {
                float mx = sc[0] * 0.35355339059327373f;
                #pragma unroll
                for (int h = 0; h < 8; h++) { sc[h] *= 0.35355339059327373f; mx = fmaxf(mx, sc[h]); }
                float sum = 0.f;
                #pragma unroll
                for (int h = 0; h < 8; h++) { sc[h] = __expf(sc[h] - mx); sum += sc[h]; }
                float inv = 1.f / sum;
                #pragma unroll
                for (int h = 0; h < 8; h++) sc[h] *= inv;
            }
            __syncthreads();
        } else if (p < 4) {
            int q = p - 2;
            #pragma unroll
            for (int j = 0; j < 32; j++) {
                int jg = q * 32 + j;
                float gv = __ldg(g_G1T + (size_t)(64 + jg) * (BB * SS) + gbs);
                float yf = av * gv + db[r * 33 + j];
                float vv = fmaxf(rstd * (yf - mu * s1v[jg]) + s2v[jg], 0.f);
                db[r * 33 + j] = sc[jg >> 3] * vv;
            }
            __syncthreads();
            {
                int col = tid & 31, qq = tid >> 5;
                float s = 0.f;
                int rr0 = qq * 32;
                #pragma unroll 8
                for (int rr = rr0; rr < rr0 + 32; rr++) s += db[rr * 33 + col];
                red[qq * 32 + col] = s;
            }
            __syncthreads();
            if (tid < 32) {
                float s = ((red[tid] + red[32 + tid]) + (red[64 + tid] + red[96 + tid]))
                        + ((red[128 + tid] + red[160 + tid]) + (red[192 + tid] + red[224 + tid]));
                g_o[(size_t)bd * 64 + q * 32 + tid] = s;
            }
            __syncthreads();
        } else {
            int q = p - 4;
            #pragma unroll
            for (int j = 0; j < 32; j++) {
                int jg = q * 32 + j;
                float gv = __ldg(g_G1T + (size_t)(128 + jg) * (BB * SS) + gbs);
                float y = av * gv + db[r * 33 + j] + av * wds[jg] + bes[jg];
                db[r * 33 + j] = fmaxf(y, 0.f);
            }
            __syncthreads();
            #pragma unroll 4
            for (int rr = 0; rr < 32; rr++) {
                int row = wid * 32 + rr;
                outE[((size_t)(b * SS + row) * DD + d) * EE + q * 32 + lane] = db[row * 33 + lane];
            }
            if (p == 4) __syncthreads();
        }
    }
}

// ---------------- finalize: V_dst_out = V_dst + relu(o @ Wo + bo); also outA = 1 ----------------
__global__ void __launch_bounds__(128) fin_kernel(
    const float* __restrict__ Vdst, const float* __restrict__ Wo,
    const float* __restrict__ bo, float* __restrict__ outV,
    float* __restrict__ outA) {
    __shared__ float os[64];
    int bd = blockIdx.x;
    int tid = threadIdx.x;
    if (tid < 64) os[tid] = g_o[(size_t)bd * 64 + tid];
    outA[bd * 256 + tid] = 1.0f;
    outA[bd * 256 + 128 + tid] = 1.0f;
    __syncthreads();
    float a = bo[tid];
    #pragma unroll 4
    for (int t = 0; t < 64; t++) a += os[t] * __ldg(Wo + t * VV + tid);
    outV[bd * VV + tid] = Vdst[bd * VV + tid] + fmaxf(a, 0.f);
}

// ---------------- launch ----------------
extern "C" void kernel_launch(void* const* d_in, const int* in_sizes, int n_in,
                              void* d_out, int out_size) {
    const float* V_src = (const float*)d_in[0];
    const float* V_dst = (const float*)d_in[1];
    const float* E     = (const float*)d_in[2];
    const float* A     = (const float*)d_in[3];
    const float* g_vd  = (const float*)d_in[4];
    const float* b_vd  = (const float*)d_in[5];
    const float* g_in  = (const float*)d_in[6];
    const float* b_in  = (const float*)d_in[7];
    const float* Wq    = (const float*)d_in[8];
    const float* bq    = (const float*)d_in[9];
    const float* Wk    = (const float*)d_in[10];
    const float* bk    = (const float*)d_in[11];
    const float* Wv    = (const float*)d_in[12];
    const float* bv    = (const float*)d_in[13];
    const float* Wo    = (const float*)d_in[14];
    const float* bo    = (const float*)d_in[15];
    const float* We    = (const float*)d_in[16];
    const float* be    = (const float*)d_in[17];
    // d_in[18] = Wa, d_in[19] = ba: unused — softmax over singleton axis is exactly 1.

    float* outV = (float*)d_out;                       // [4,256,128]
    float* outE = outV + BB * DD * VV;                 // [4,256,256,64]
    float* outA = outE + (size_t)BB * SS * DD * EE;    // [4,256,256]

    const int SMEM_G1 = (1024 + 64 * 192) * (int)sizeof(float);
    cudaFuncSetAttribute(main_kernel, cudaFuncAttributeMaxDynamicSharedMemorySize, SMEM_MAIN);
    cudaFuncSetAttribute(g1_kernel, cudaFuncAttributeMaxDynamicSharedMemorySize, SMEM_G1);

    prep_all<<<321, 192>>>(g_in, b_in, Wk, bk, Wv, bv, We);
    g1_kernel<<<BB * SS / 8, 256, SMEM_G1>>>(V_src);
    qwd_kernel<<<BB * DD / 4, 512>>>(V_dst, g_vd, b_vd, Wq, bq, We);
    main_kernel<<<BB * DD, 256, SMEM_MAIN>>>(E, A, be, outE);
    fin_kernel<<<BB * DD, 128>>>(V_dst, Wo, bo, outV, outA);
}